// round 12
// baseline (speedup 1.0000x reference)
#include <cuda_runtime.h>
#include <cstdint>

// ---------------------------------------------------------------------------
// Scratch (static __device__ — no allocation in kernel_launch)
// ---------------------------------------------------------------------------
static __device__ float g_X[8 * 384 * 1024];   // tf32-rounded input activations
static __device__ float g_Y[8 * 1152 * 1024];  // V lives here [b][768+c][1024]
static __device__ float g_QT[8 * 12 * 1024 * 32];  // Q transposed [b][h][n][d]
static __device__ float g_KT[8 * 12 * 1024 * 32];  // K transposed [b][h][n][d]
static __device__ float g_O[8 * 384 * 1024];   // attention output [b][384][1024]
static __device__ float g_Wqkv[1152 * 384];    // [q_w*scale ; kv_w] tf32-rounded
static __device__ float g_Wp[384 * 384];       // proj_w tf32-rounded
static __device__ float g_Bqkv[1152];          // [q_b*scale ; kv_b]
static __device__ float g_rpbT[12 * 3972];     // rpb_table transposed [head][pad 3972]

// ---------------------------------------------------------------------------
// Helpers
// ---------------------------------------------------------------------------
__device__ __forceinline__ unsigned tf32_bits(float x) {
    unsigned u;
    asm("cvt.rna.tf32.f32 %0, %1;" : "=r"(u) : "f"(x));
    return u;
}
__device__ __forceinline__ float tf32f(float x) { return __uint_as_float(tf32_bits(x)); }

__device__ __forceinline__ float fast_ex2(float x) {
    float y;
    asm("ex2.approx.f32 %0, %1;" : "=f"(y) : "f"(x));
    return y;
}

__device__ __forceinline__ void mma_tf32(float* c,
                                         unsigned a0, unsigned a1, unsigned a2, unsigned a3,
                                         unsigned b0, unsigned b1) {
    asm volatile(
        "mma.sync.aligned.m16n8k8.row.col.f32.tf32.tf32.f32 "
        "{%0,%1,%2,%3}, {%4,%5,%6,%7}, {%8,%9}, {%0,%1,%2,%3};\n"
        : "+f"(c[0]), "+f"(c[1]), "+f"(c[2]), "+f"(c[3])
        : "r"(a0), "r"(a1), "r"(a2), "r"(a3), "r"(b0), "r"(b1));
}

// ldmatrix x4: four 8x4 b32 tiles; lane l receives element (row l/4, col l%4)
// of the tile addressed by lanes [8*t, 8*t+8).
__device__ __forceinline__ void ldsm_x4(unsigned& r0, unsigned& r1, unsigned& r2, unsigned& r3,
                                        unsigned addr) {
    asm volatile("ldmatrix.sync.aligned.m8n8.x4.shared.b16 {%0,%1,%2,%3}, [%4];\n"
                 : "=r"(r0), "=r"(r1), "=r"(r2), "=r"(r3) : "r"(addr));
}

__device__ __forceinline__ unsigned smem_u32(const void* p) {
    return (unsigned)__cvta_generic_to_shared(p);
}

__device__ __forceinline__ void cp_async16(float* smem_dst, const float* gmem_src) {
    unsigned s = (unsigned)__cvta_generic_to_shared(smem_dst);
    asm volatile("cp.async.cg.shared.global [%0], [%1], 16;\n" :: "r"(s), "l"(gmem_src));
}
__device__ __forceinline__ void cp_commit() { asm volatile("cp.async.commit_group;\n"); }
__device__ __forceinline__ void cp_wait0() { asm volatile("cp.async.wait_group 0;\n"); }
__device__ __forceinline__ void cp_wait1() { asm volatile("cp.async.wait_group 1;\n"); }

// ---------------------------------------------------------------------------
// One-time operand rounding / transpose kernels
// ---------------------------------------------------------------------------
__global__ void convert_x_kernel(const float* __restrict__ x) {
    const float4* src = reinterpret_cast<const float4*>(x);
    float4* dst = reinterpret_cast<float4*>(g_X);
    const int stride = gridDim.x * blockDim.x;
    for (int i = blockIdx.x * blockDim.x + threadIdx.x; i < 786432; i += stride) {
        float4 v = src[i];
        v.x = tf32f(v.x); v.y = tf32f(v.y); v.z = tf32f(v.z); v.w = tf32f(v.w);
        dst[i] = v;
    }
}

__global__ void convert_w_kernel(const float* __restrict__ qw, const float* __restrict__ kvw,
                                 const float* __restrict__ pw, const float* __restrict__ qb,
                                 const float* __restrict__ kvb, const float* __restrict__ rpb) {
    const float scale = 0.17677669529663687f;  // 32^-0.5 folded into Q path
    const int stride = gridDim.x * blockDim.x;
    const int t = blockIdx.x * blockDim.x + threadIdx.x;
    for (int i = t; i < 147456; i += stride) g_Wqkv[i] = tf32f(qw[i] * scale);
    for (int i = t; i < 294912; i += stride) g_Wqkv[147456 + i] = tf32f(kvw[i]);
    for (int i = t; i < 147456; i += stride) g_Wp[i] = tf32f(pw[i]);
    for (int i = t; i < 384; i += stride) g_Bqkv[i] = qb[i] * scale;
    for (int i = t; i < 768; i += stride) g_Bqkv[384 + i] = kvb[i];
    for (int i = t; i < 12 * 3969; i += stride) {
        int h = i / 3969, j = i - h * 3969;
        g_rpbT[h * 3972 + j] = rpb[j * 12 + h];
    }
}

// ---------------------------------------------------------------------------
// Batched GEMM, cp.async 2-stage pipeline, A-frags via ldmatrix.
// C[b][m][n] = sum_k W[m][k] * X[b][k][n] + bias[m].  K=384, N=1024.
// Tiles 128x128, k-chunk 32. 8 warps 4(m)x2(n): 32x64 per warp.
// QKV=true: Q rows (<384) / K rows (<768) stored transposed to g_QT/g_KT,
// V rows stored normally to C; everything tf32-rounded.
// ---------------------------------------------------------------------------
constexpr int GEMM_SMEM_BYTES = 2 * (128 * 36 + 32 * 136) * 4;  // 71,680

template <bool QKV>
__global__ __launch_bounds__(256, 2)
void gemm_async_kernel(const float* __restrict__ W, const float* __restrict__ X,
                       const float* __restrict__ bias, float* __restrict__ C,
                       long xStride, long cStride) {
    extern __shared__ float sm[];
    float* As = sm;                 // [2][128*36]
    float* Bs = sm + 2 * 128 * 36;  // [2][32*136]

    const int b  = blockIdx.z;
    const int m0 = blockIdx.y * 128;
    const int n0 = blockIdx.x * 128;
    const float* Xb = X + (long)b * xStride;
    float*       Cb = C + (long)b * cStride;

    const int tid  = threadIdx.x;
    const int warp = tid >> 5, lane = tid & 31;
    const int gr = lane >> 2, tc = lane & 3;
    const int mw = warp >> 1, nw = warp & 1;   // warp tile: rows mw*32, cols nw*64

    // ldmatrix lane address offsets for A fragments (rows m, k contiguous)
    const unsigned As_u32 = smem_u32(As);
    unsigned aoff[2];
#pragma unroll
    for (int jt = 0; jt < 2; jt++)
        aoff[jt] = ((mw * 32 + jt * 16 + ((lane & 8) ? 8 : 0) + (lane & 7)) * 36 +
                    ((lane & 16) ? 4 : 0)) * 4;

    auto issue_tile = [&](int kt) {
        float* A  = As + (kt & 1) * (128 * 36);
        float* Bt = Bs + (kt & 1) * (32 * 136);
        const int k0 = kt * 32;
#pragma unroll
        for (int i = 0; i < 4; i++) {
            int idx = tid + i * 256;          // 1024 16B chunks for A (128x32)
            int r = idx >> 3, cc = (idx & 7) << 2;
            cp_async16(A + r * 36 + cc, W + (long)(m0 + r) * 384 + k0 + cc);
        }
#pragma unroll
        for (int i = 0; i < 4; i++) {
            int idx = tid + i * 256;          // 1024 16B chunks for B (32x128)
            int r = idx >> 5, cc = (idx & 31) << 2;
            cp_async16(Bt + r * 136 + cc, Xb + (long)(k0 + r) * 1024 + n0 + cc);
        }
        cp_commit();
    };

    float acc[2][8][4];
#pragma unroll
    for (int j = 0; j < 2; j++)
#pragma unroll
        for (int i = 0; i < 8; i++) { acc[j][i][0] = 0.f; acc[j][i][1] = 0.f; acc[j][i][2] = 0.f; acc[j][i][3] = 0.f; }

    issue_tile(0);
    issue_tile(1);

    for (int kt = 0; kt < 12; kt++) {
        if (kt < 11) cp_wait1(); else cp_wait0();
        __syncthreads();

        const unsigned Abase = As_u32 + (kt & 1) * (128 * 36 * 4);
        float* Bt = Bs + (kt & 1) * (32 * 136);
#pragma unroll
        for (int ks = 0; ks < 4; ks++) {
            const int kk = ks * 8;
            unsigned a[2][4];
#pragma unroll
            for (int jt = 0; jt < 2; jt++)
                ldsm_x4(a[jt][0], a[jt][1], a[jt][2], a[jt][3], Abase + aoff[jt] + kk * 4);
#pragma unroll
            for (int nt = 0; nt < 8; nt++) {
                const int cc = nw * 64 + nt * 8 + gr;
                unsigned b0 = __float_as_uint(Bt[(kk + tc) * 136 + cc]);
                unsigned b1 = __float_as_uint(Bt[(kk + tc + 4) * 136 + cc]);
                mma_tf32(acc[0][nt], a[0][0], a[0][1], a[0][2], a[0][3], b0, b1);
                mma_tf32(acc[1][nt], a[1][0], a[1][1], a[1][2], a[1][3], b0, b1);
            }
        }
        __syncthreads();
        if (kt + 2 < 12) issue_tile(kt + 2);
    }

    if (QKV && m0 < 768) {
        // Q or K rows -> transposed [b][h][n][d] store (sector-aligned STG.32)
        float* T = (m0 < 384) ? g_QT : g_KT;
        const int cbase = (m0 < 384) ? 0 : 384;
#pragma unroll
        for (int jt = 0; jt < 2; jt++) {
            const int rb = m0 + mw * 32 + jt * 16 + gr;
            const int h = (rb - cbase) >> 5;
            const int d = rb & 31;
            const float bz0 = bias[rb], bz1 = bias[rb + 8];
            float* Tb = T + ((long)(b * 12 + h) * 1024) * 32;
#pragma unroll
            for (int nt = 0; nt < 8; nt++) {
                const int cc = n0 + nw * 64 + nt * 8 + tc * 2;
                Tb[(long)cc * 32 + d]           = tf32f(acc[jt][nt][0] + bz0);
                Tb[(long)(cc + 1) * 32 + d]     = tf32f(acc[jt][nt][1] + bz0);
                Tb[(long)cc * 32 + d + 8]       = tf32f(acc[jt][nt][2] + bz1);
                Tb[(long)(cc + 1) * 32 + d + 8] = tf32f(acc[jt][nt][3] + bz1);
            }
        }
    } else {
#pragma unroll
        for (int jt = 0; jt < 2; jt++) {
            const int rb = m0 + mw * 32 + jt * 16 + gr;
            const float bz0 = bias[rb], bz1 = bias[rb + 8];
#pragma unroll
            for (int nt = 0; nt < 8; nt++) {
                const int cc = n0 + nw * 64 + nt * 8 + tc * 2;
                float o00 = acc[jt][nt][0] + bz0, o01 = acc[jt][nt][1] + bz0;
                float o10 = acc[jt][nt][2] + bz1, o11 = acc[jt][nt][3] + bz1;
                if (QKV) { o00 = tf32f(o00); o01 = tf32f(o01); o10 = tf32f(o10); o11 = tf32f(o11); }
                *reinterpret_cast<float2*>(Cb + (long)rb * 1024 + cc)       = make_float2(o00, o01);
                *reinterpret_cast<float2*>(Cb + (long)(rb + 8) * 1024 + cc) = make_float2(o10, o11);
            }
        }
    }
}

// ---------------------------------------------------------------------------
// Flash attention, all fragments via ldmatrix.
// Q,K in smem as [n][d] (stride 36); V as [d][n] (stride 132).
// Key-column permutation folded into K ldmatrix addresses so the exp'd
// S C-frag IS the B-frag of  O^T = V * P^T  (direct [d][n] stores).
// Grid: (qblock 0..7, head 0..11, batch 0..7). 256 threads, 2 CTAs/SM.
// ---------------------------------------------------------------------------
constexpr int A_QS  = 0;                    // 128*36 = 4608
constexpr int A_KS  = 4608;                 // 2 stages * 4608
constexpr int A_VS  = A_KS + 2 * 4608;      // 2 stages * 4224
constexpr int A_RPB = A_VS + 2 * 4224;      // 3972
constexpr int ATTN_SMEM_BYTES = (A_RPB + 3972) * 4;  // 104,976 B

__global__ __launch_bounds__(256, 2)
void attn_async_kernel(float* __restrict__ Oout) {
    extern __shared__ float sm[];
    float* Qs    = sm + A_QS;    // [128 n][36] (32 d used)
    float* Ksb   = sm + A_KS;    // 2 x [128 n][36]
    float* Vsb   = sm + A_VS;    // 2 x [32 d][132]
    float* rpb_s = sm + A_RPB;

    const int qb = blockIdx.x, h = blockIdx.y, b = blockIdx.z;
    const int tid  = threadIdx.x;
    const int warp = tid >> 5, lane = tid & 31;
    const int gr = lane >> 2, tc = lane & 3;

    const float* QgT = g_QT + (long)(b * 12 + h) * 1024 * 32 + (long)qb * 128 * 32;
    const float* KgT = g_KT + (long)(b * 12 + h) * 1024 * 32;
    const float* Vg  = g_Y + ((long)b * 1152 + 768 + h * 32) * 1024;

    // Per-lane ldmatrix address offsets (bytes)
    const int j8 = lane & 7;
    const int pj = (j8 >> 1) | ((j8 & 1) << 2);   // key-column permutation
    const unsigned q_off = ((warp * 16 + ((lane & 8) ? 8 : 0) + j8) * 36 +
                            ((lane & 16) ? 4 : 0)) * 4;
    const unsigned k_off = ((((lane & 16) >> 1) + pj) * 36 + ((lane & 8) ? 4 : 0)) * 4;
    const unsigned v_off = ((((lane & 8) ? 8 : 0) + j8) * 132 + ((lane & 16) ? 4 : 0)) * 4;
    const unsigned Qs_u32 = smem_u32(Qs), Ks_u32 = smem_u32(Ksb), Vs_u32 = smem_u32(Vsb);

    // Group 0: Q tile (128x32) + K block 0 (128x32) + V block 0 (32x128) + bias
#pragma unroll
    for (int i = 0; i < 4; i++) {
        int idx = tid + i * 256;
        {   // Q, K: [n][d] rows of 32 floats = 8 chunks
            int n = idx >> 3, ch = (idx & 7) << 2;
            cp_async16(Qs + n * 36 + ch, QgT + (long)n * 32 + ch);
            cp_async16(Ksb + n * 36 + ch, KgT + (long)n * 32 + ch);
        }
        {   // V: [d][n] rows of 128 floats = 32 chunks
            int d = idx >> 5, c4 = (idx & 31) << 2;
            cp_async16(Vsb + d * 132 + c4, Vg + (long)d * 1024 + c4);
        }
    }
    {
        const float* rpbh = g_rpbT + h * 3972;
        for (int i = tid * 4; i < 3972; i += 1024)
            cp_async16(rpb_s + i, rpbh + i);
    }
    cp_commit();

    float oaccT[2][2][4];   // [d-tile][q-tile][c0..c3]; O^T[d][q]
#pragma unroll
    for (int mt = 0; mt < 2; mt++)
#pragma unroll
        for (int qt = 0; qt < 2; qt++) { oaccT[mt][qt][0] = 0.f; oaccT[mt][qt][1] = 0.f; oaccT[mt][qt][2] = 0.f; oaccT[mt][qt][3] = 0.f; }
    float mrun0 = -1e30f, mrun1 = -1e30f, lrun0 = 0.f, lrun1 = 0.f;

    // Analytic bias row constants: idx = Abias(q) - Bm(m), Bm = (m>>5)*63 + (m&31)
    const int n0g = qb * 128 + warp * 16 + gr;
    const int Abias0 = ((n0g >> 5) + 31) * 63 + (n0g & 31) + 31;
    const int n1g = n0g + 8;
    const int Abias1 = ((n1g >> 5) + 31) * 63 + (n1g & 31) + 31;

    const float L2E = 1.4426950408889634f;

    for (int kb = 0; kb < 8; kb++) {
        if (kb < 7) {
            const int nb = kb + 1;
            float* Kn = Ksb + (nb & 1) * 4608;
            float* Vn = Vsb + (nb & 1) * 4224;
#pragma unroll
            for (int i = 0; i < 4; i++) {
                int idx = tid + i * 256;
                {
                    int n = idx >> 3, ch = (idx & 7) << 2;
                    cp_async16(Kn + n * 36 + ch, KgT + (long)(nb * 128 + n) * 32 + ch);
                }
                {
                    int d = idx >> 5, c4 = (idx & 31) << 2;
                    cp_async16(Vn + d * 132 + c4, Vg + (long)d * 1024 + nb * 128 + c4);
                }
            }
            cp_commit();
            cp_wait1();
        } else {
            cp_wait0();
        }
        __syncthreads();

        const unsigned Kbase = Ks_u32 + (kb & 1) * (4608 * 4) + k_off;
        const unsigned Vbase = Vs_u32 + (kb & 1) * (4224 * 4) + v_off;

        // S = Q^T K, fragments via ldmatrix (key cols permuted by address)
        float sacc[16][4];
#pragma unroll
        for (int i = 0; i < 16; i++) { sacc[i][0] = 0.f; sacc[i][1] = 0.f; sacc[i][2] = 0.f; sacc[i][3] = 0.f; }

#pragma unroll
        for (int ks = 0; ks < 4; ks++) {
            const int kk = ks * 8;
            unsigned a0, a1, a2, a3;
            ldsm_x4(a0, a1, a2, a3, Qs_u32 + q_off + kk * 4);
#pragma unroll
            for (int ntp = 0; ntp < 8; ntp++) {
                unsigned b00, b01, b10, b11;
                ldsm_x4(b00, b01, b10, b11, Kbase + (ntp * 576 + kk) * 4);
                mma_tf32(sacc[2 * ntp],     a0, a1, a2, a3, b00, b01);
                mma_tf32(sacc[2 * ntp + 1], a0, a1, a2, a3, b10, b11);
            }
        }

        // Bias: this thread's cols are j = nt*8 + tc and nt*8 + tc + 4
#pragma unroll
        for (int nt = 0; nt < 16; nt++) {
            const int m  = kb * 128 + nt * 8 + tc;
            const int Bm = (m >> 5) * 63 + (m & 31);
            sacc[nt][0] += rpb_s[Abias0 - Bm];
            sacc[nt][1] += rpb_s[Abias0 - Bm - 4];
            sacc[nt][2] += rpb_s[Abias1 - Bm];
            sacc[nt][3] += rpb_s[Abias1 - Bm - 4];
        }

        // Row max
        float mx0 = -1e30f, mx1 = -1e30f;
#pragma unroll
        for (int nt = 0; nt < 16; nt++) {
            mx0 = fmaxf(mx0, fmaxf(sacc[nt][0], sacc[nt][1]));
            mx1 = fmaxf(mx1, fmaxf(sacc[nt][2], sacc[nt][3]));
        }
        mx0 = fmaxf(mx0, __shfl_xor_sync(0xffffffffu, mx0, 1));
        mx0 = fmaxf(mx0, __shfl_xor_sync(0xffffffffu, mx0, 2));
        mx1 = fmaxf(mx1, __shfl_xor_sync(0xffffffffu, mx1, 1));
        mx1 = fmaxf(mx1, __shfl_xor_sync(0xffffffffu, mx1, 2));
        const float mnew0 = fmaxf(mrun0, mx0);
        const float mnew1 = fmaxf(mrun1, mx1);
        const float alpha0 = fast_ex2((mrun0 - mnew0) * L2E);
        const float alpha1 = fast_ex2((mrun1 - mnew1) * L2E);
        mrun0 = mnew0; mrun1 = mnew1;

        // Per-q-column alphas for the O^T accumulator
        const float aq0 = __shfl_sync(0xffffffffu, alpha0, 8 * tc);
        const float aq1 = __shfl_sync(0xffffffffu, alpha0, 8 * tc + 4);
        const float aq2 = __shfl_sync(0xffffffffu, alpha1, 8 * tc);
        const float aq3 = __shfl_sync(0xffffffffu, alpha1, 8 * tc + 4);
#pragma unroll
        for (int mt = 0; mt < 2; mt++) {
            oaccT[mt][0][0] *= aq0; oaccT[mt][0][1] *= aq1;
            oaccT[mt][0][2] *= aq0; oaccT[mt][0][3] *= aq1;
            oaccT[mt][1][0] *= aq2; oaccT[mt][1][1] *= aq3;
            oaccT[mt][1][2] *= aq2; oaccT[mt][1][3] *= aq3;
        }

        // exp -> P regs (B-frag layout) -> O^T += V * P^T  (V frags via ldmatrix)
        float sum0 = 0.f, sum1 = 0.f;
#pragma unroll
        for (int nt = 0; nt < 16; nt++) {
            float p0 = fast_ex2((sacc[nt][0] - mnew0) * L2E);  // P[gr][tc]
            float p1 = fast_ex2((sacc[nt][1] - mnew0) * L2E);  // P[gr][tc+4]
            float p2 = fast_ex2((sacc[nt][2] - mnew1) * L2E);  // P[gr+8][tc]
            float p3 = fast_ex2((sacc[nt][3] - mnew1) * L2E);  // P[gr+8][tc+4]
            sum0 += p0 + p1; sum1 += p2 + p3;

            unsigned u0 = tf32_bits(p0), u1 = tf32_bits(p1);
            unsigned u2 = tf32_bits(p2), u3 = tf32_bits(p3);

            unsigned va0, va1, va2, va3;
            ldsm_x4(va0, va1, va2, va3, Vbase + (nt * 8) * 4);
            mma_tf32(oaccT[0][0], va0, va1, va2, va3, u0, u1);
            mma_tf32(oaccT[0][1], va0, va1, va2, va3, u2, u3);
            ldsm_x4(va0, va1, va2, va3, Vbase + (16 * 132 + nt * 8) * 4);
            mma_tf32(oaccT[1][0], va0, va1, va2, va3, u0, u1);
            mma_tf32(oaccT[1][1], va0, va1, va2, va3, u2, u3);
        }
        sum0 += __shfl_xor_sync(0xffffffffu, sum0, 1);
        sum0 += __shfl_xor_sync(0xffffffffu, sum0, 2);
        sum1 += __shfl_xor_sync(0xffffffffu, sum1, 1);
        sum1 += __shfl_xor_sync(0xffffffffu, sum1, 2);
        lrun0 = lrun0 * alpha0 + sum0;
        lrun1 = lrun1 * alpha1 + sum1;

        __syncthreads();  // all warps done with K/V[cur] before refill
    }

    // Finalize: per-q-column 1/l, direct [d][n] stores (O^T rows are d)
    const float inv0 = 1.f / lrun0;
    const float inv1 = 1.f / lrun1;
    const float iq0 = __shfl_sync(0xffffffffu, inv0, 8 * tc);
    const float iq1 = __shfl_sync(0xffffffffu, inv0, 8 * tc + 4);
    const float iq2 = __shfl_sync(0xffffffffu, inv1, 8 * tc);
    const float iq3 = __shfl_sync(0xffffffffu, inv1, 8 * tc + 4);

    float* Ob = Oout + ((long)b * 384 + h * 32) * 1024 + qb * 128 + warp * 16;
#pragma unroll
    for (int mt = 0; mt < 2; mt++) {
#pragma unroll
        for (int qt = 0; qt < 2; qt++) {
            const float sA = qt ? iq2 : iq0;
            const float sB = qt ? iq3 : iq1;
            const int col = qt * 8 + tc * 2;
            const int r   = mt * 16 + gr;
            *reinterpret_cast<float2*>(Ob + (long)r * 1024 + col) =
                make_float2(tf32f(oaccT[mt][qt][0] * sA), tf32f(oaccT[mt][qt][1] * sB));
            *reinterpret_cast<float2*>(Ob + (long)(r + 8) * 1024 + col) =
                make_float2(tf32f(oaccT[mt][qt][2] * sA), tf32f(oaccT[mt][qt][3] * sB));
        }
    }
}

// ---------------------------------------------------------------------------
// Launch
// ---------------------------------------------------------------------------
extern "C" void kernel_launch(void* const* d_in, const int* in_sizes, int n_in,
                              void* d_out, int out_size) {
    (void)in_sizes; (void)n_in; (void)out_size;
    const float* x      = (const float*)d_in[0];
    const float* q_w    = (const float*)d_in[1];
    const float* q_b    = (const float*)d_in[2];
    const float* kv_w   = (const float*)d_in[3];
    const float* kv_b   = (const float*)d_in[4];
    const float* proj_w = (const float*)d_in[5];
    const float* proj_b = (const float*)d_in[6];
    const float* rpb    = (const float*)d_in[7];
    // d_in[8] = rel_index: recomputed analytically on device, unused.
    float* out = (float*)d_out;

    float* X = nullptr; cudaGetSymbolAddress((void**)&X, g_X);
    float* Y = nullptr; cudaGetSymbolAddress((void**)&Y, g_Y);
    float* O = nullptr; cudaGetSymbolAddress((void**)&O, g_O);
    float* Wqkv = nullptr; cudaGetSymbolAddress((void**)&Wqkv, g_Wqkv);
    float* Wp   = nullptr; cudaGetSymbolAddress((void**)&Wp, g_Wp);
    float* Bqkv = nullptr; cudaGetSymbolAddress((void**)&Bqkv, g_Bqkv);

    cudaFuncSetAttribute(gemm_async_kernel<true>,
                         cudaFuncAttributeMaxDynamicSharedMemorySize, GEMM_SMEM_BYTES);
    cudaFuncSetAttribute(gemm_async_kernel<false>,
                         cudaFuncAttributeMaxDynamicSharedMemorySize, GEMM_SMEM_BYTES);
    cudaFuncSetAttribute(attn_async_kernel,
                         cudaFuncAttributeMaxDynamicSharedMemorySize, ATTN_SMEM_BYTES);

    dim3 blk(256);
    // Pre-round operands to tf32 so cp.async paths are numerically exact RNA
    convert_x_kernel<<<768, blk>>>(x);
    convert_w_kernel<<<288, blk>>>(q_w, kv_w, proj_w, q_b, kv_b, rpb);
    // Fused QKV projection: Q,K -> g_QT/g_KT transposed; V -> g_Y rows 768+
    gemm_async_kernel<true><<<dim3(8, 9, 8), blk, GEMM_SMEM_BYTES>>>(
        Wqkv, X, Bqkv, Y, 384L * 1024, 1152L * 1024);
    // Flash attention -> g_O (rounded)
    attn_async_kernel<<<dim3(8, 12, 8), blk, ATTN_SMEM_BYTES>>>(O);
    // Output projection -> d_out (not rounded)
    gemm_async_kernel<false><<<dim3(8, 3, 8), blk, GEMM_SMEM_BYTES>>>(
        Wp, O, proj_b, out, 384L * 1024, 384L * 1024);
}

// round 13
// speedup vs baseline: 1.5133x; 1.5133x over previous
#include <cuda_runtime.h>
#include <cuda_fp16.h>
#include <cstdint>

// ---------------------------------------------------------------------------
// Scratch (static __device__ — no allocation in kernel_launch)
// ---------------------------------------------------------------------------
static __device__ __half g_X[8 * 384 * 1024];        // fp16 input activations
static __device__ __half g_QT[8 * 12 * 1024 * 32];   // Q transposed [b][h][n][d]
static __device__ __half g_KT[8 * 12 * 1024 * 32];   // K transposed [b][h][n][d]
static __device__ __half g_V[8 * 384 * 1024];        // V [b][c][n]
static __device__ __half g_O[8 * 384 * 1024];        // attention out [b][c][n]
static __device__ __half g_Wqkv[1152 * 384];         // [q_w*scale ; kv_w]
static __device__ __half g_Wp[384 * 384];            // proj_w
static __device__ float  g_Bqkv[1152];               // [q_b*scale ; kv_b]
static __device__ float  g_rpbT[12 * 3972];          // rpb transposed [head][pad]

// ---------------------------------------------------------------------------
// Helpers
// ---------------------------------------------------------------------------
__device__ __forceinline__ float fast_ex2(float x) {
    float y;
    asm("ex2.approx.f32 %0, %1;" : "=f"(y) : "f"(x));
    return y;
}

// m16n8k16 fp16 mma, fp32 accumulate. A: 4 regs (8 halves), B: 2 regs (4 halves).
__device__ __forceinline__ void mma16(float* c,
                                      unsigned a0, unsigned a1, unsigned a2, unsigned a3,
                                      unsigned b0, unsigned b1) {
    asm volatile(
        "mma.sync.aligned.m16n8k16.row.col.f32.f16.f16.f32 "
        "{%0,%1,%2,%3}, {%4,%5,%6,%7}, {%8,%9}, {%0,%1,%2,%3};\n"
        : "+f"(c[0]), "+f"(c[1]), "+f"(c[2]), "+f"(c[3])
        : "r"(a0), "r"(a1), "r"(a2), "r"(a3), "r"(b0), "r"(b1));
}

__device__ __forceinline__ void ldsm_x4(unsigned& r0, unsigned& r1, unsigned& r2, unsigned& r3,
                                        unsigned addr) {
    asm volatile("ldmatrix.sync.aligned.m8n8.x4.shared.b16 {%0,%1,%2,%3}, [%4];\n"
                 : "=r"(r0), "=r"(r1), "=r"(r2), "=r"(r3) : "r"(addr));
}
__device__ __forceinline__ void ldsm_x4_t(unsigned& r0, unsigned& r1, unsigned& r2, unsigned& r3,
                                          unsigned addr) {
    asm volatile("ldmatrix.sync.aligned.m8n8.x4.trans.shared.b16 {%0,%1,%2,%3}, [%4];\n"
                 : "=r"(r0), "=r"(r1), "=r"(r2), "=r"(r3) : "r"(addr));
}

__device__ __forceinline__ unsigned smem_u32(const void* p) {
    return (unsigned)__cvta_generic_to_shared(p);
}
__device__ __forceinline__ void cp_async16(void* smem_dst, const void* gmem_src) {
    unsigned s = (unsigned)__cvta_generic_to_shared(smem_dst);
    asm volatile("cp.async.cg.shared.global [%0], [%1], 16;\n" :: "r"(s), "l"(gmem_src));
}
__device__ __forceinline__ void cp_commit() { asm volatile("cp.async.commit_group;\n"); }
__device__ __forceinline__ void cp_wait0() { asm volatile("cp.async.wait_group 0;\n"); }
__device__ __forceinline__ void cp_wait1() { asm volatile("cp.async.wait_group 1;\n"); }

__device__ __forceinline__ unsigned h2u(__half2 h) { return *reinterpret_cast<unsigned*>(&h); }

// ---------------------------------------------------------------------------
// One-time conversion kernels
// ---------------------------------------------------------------------------
__global__ void convert_x_kernel(const float* __restrict__ x) {
    const float4* src = reinterpret_cast<const float4*>(x);
    __half2* dst = reinterpret_cast<__half2*>(g_X);
    const int stride = gridDim.x * blockDim.x;
    for (int i = blockIdx.x * blockDim.x + threadIdx.x; i < 786432; i += stride) {
        float4 v = src[i];
        dst[2 * i]     = __floats2half2_rn(v.x, v.y);
        dst[2 * i + 1] = __floats2half2_rn(v.z, v.w);
    }
}

__global__ void convert_w_kernel(const float* __restrict__ qw, const float* __restrict__ kvw,
                                 const float* __restrict__ pw, const float* __restrict__ qb,
                                 const float* __restrict__ kvb, const float* __restrict__ rpb) {
    const float scale = 0.17677669529663687f;  // 32^-0.5 folded into Q path
    const int stride = gridDim.x * blockDim.x;
    const int t = blockIdx.x * blockDim.x + threadIdx.x;
    for (int i = t; i < 147456; i += stride) g_Wqkv[i] = __float2half_rn(qw[i] * scale);
    for (int i = t; i < 294912; i += stride) g_Wqkv[147456 + i] = __float2half_rn(kvw[i]);
    for (int i = t; i < 147456; i += stride) g_Wp[i] = __float2half_rn(pw[i]);
    for (int i = t; i < 384; i += stride) g_Bqkv[i] = qb[i] * scale;
    for (int i = t; i < 768; i += stride) g_Bqkv[384 + i] = kvb[i];
    for (int i = t; i < 12 * 3969; i += stride) {
        int h = i / 3969, j = i - h * 3969;
        g_rpbT[h * 3972 + j] = rpb[j * 12 + h];
    }
}

// ---------------------------------------------------------------------------
// Batched fp16 GEMM, cp.async 2-stage, all fragments via ldmatrix.
// C[b][m][n] = sum_k W[m][k] * X[b][k][n] + bias[m].  K=384, N=1024.
// Tiles 128x128, k-chunk 32 (2 mma k-steps). 8 warps 4(m)x2(n): 32x64/warp.
// QKV=true: Q rows (<384) -> g_QT transposed, K rows (<768) -> g_KT
//           transposed, V rows -> g_V (half). QKV=false: float C out.
// ---------------------------------------------------------------------------
constexpr int GA_STRIDE = 40;    // halves per A row (80B: 16B-aligned, conflict-free)
constexpr int GB_STRIDE = 136;   // halves per B row (272B)
constexpr int GA_TILE = 128 * GA_STRIDE;  // halves per stage
constexpr int GB_TILE = 32 * GB_STRIDE;
constexpr int GEMM_SMEM_BYTES = 2 * (GA_TILE + GB_TILE) * 2;  // 38,656 B

template <bool QKV>
__global__ __launch_bounds__(256, 2)
void gemm_async_kernel(const __half* __restrict__ W, const __half* __restrict__ X,
                       const float* __restrict__ bias, void* __restrict__ Cout,
                       long xStride, long cStride) {
    extern __shared__ __half smh[];
    __half* As = smh;
    __half* Bs = smh + 2 * GA_TILE;

    const int b  = blockIdx.z;
    const int m0 = blockIdx.y * 128;
    const int n0 = blockIdx.x * 128;
    const __half* Xb = X + (long)b * xStride;

    const int tid  = threadIdx.x;
    const int warp = tid >> 5, lane = tid & 31;
    const int gr = lane >> 2, tc = lane & 3;
    const int mw = warp >> 1, nw = warp & 1;   // warp tile: rows mw*32, cols nw*64

    const unsigned As_u32 = smem_u32(As), Bs_u32 = smem_u32(Bs);
    // A ldmatrix (non-trans) lane offset: rows m, k contiguous
    unsigned aoff[2];
#pragma unroll
    for (int jt = 0; jt < 2; jt++)
        aoff[jt] = ((mw * 32 + jt * 16 + (lane & 8) + (lane & 7)) * GA_STRIDE +
                    ((lane & 16) >> 1)) * 2;
    // B ldmatrix.trans lane offset: rows k, n contiguous
    const unsigned boff = (((lane & 8) + (lane & 7)) * GB_STRIDE +
                           nw * 64 + ((lane & 16) ? 8 : 0)) * 2;

    auto issue_tile = [&](int kt) {
        __half* A  = As + (kt & 1) * GA_TILE;
        __half* Bt = Bs + (kt & 1) * GB_TILE;
        const int k0 = kt * 32;
#pragma unroll
        for (int i = 0; i < 2; i++) {
            int idx = tid + i * 256;           // 512 chunks: A 128x32 halves
            int r = idx >> 2, ch = (idx & 3) << 3;
            cp_async16(A + r * GA_STRIDE + ch, W + (long)(m0 + r) * 384 + k0 + ch);
        }
#pragma unroll
        for (int i = 0; i < 2; i++) {
            int idx = tid + i * 256;           // 512 chunks: B 32x128 halves
            int r = idx >> 4, ch = (idx & 15) << 3;
            cp_async16(Bt + r * GB_STRIDE + ch, Xb + (long)(k0 + r) * 1024 + n0 + ch);
        }
        cp_commit();
    };

    float acc[2][8][4];
#pragma unroll
    for (int j = 0; j < 2; j++)
#pragma unroll
        for (int i = 0; i < 8; i++) { acc[j][i][0] = 0.f; acc[j][i][1] = 0.f; acc[j][i][2] = 0.f; acc[j][i][3] = 0.f; }

    issue_tile(0);
    issue_tile(1);

    for (int kt = 0; kt < 12; kt++) {
        if (kt < 11) cp_wait1(); else cp_wait0();
        __syncthreads();

        const unsigned Abase = As_u32 + (kt & 1) * (GA_TILE * 2);
        const unsigned Bbase = Bs_u32 + (kt & 1) * (GB_TILE * 2);
#pragma unroll
        for (int ks = 0; ks < 2; ks++) {
            const int kk = ks * 16;
            unsigned a[2][4];
#pragma unroll
            for (int jt = 0; jt < 2; jt++)
                ldsm_x4(a[jt][0], a[jt][1], a[jt][2], a[jt][3], Abase + aoff[jt] + kk * 2);
            unsigned bf[8][2];
#pragma unroll
            for (int bi = 0; bi < 4; bi++)
                ldsm_x4_t(bf[2 * bi][0], bf[2 * bi][1], bf[2 * bi + 1][0], bf[2 * bi + 1][1],
                          Bbase + boff + (kk * GB_STRIDE + bi * 16) * 2);
#pragma unroll
            for (int nt = 0; nt < 8; nt++) {
                mma16(acc[0][nt], a[0][0], a[0][1], a[0][2], a[0][3], bf[nt][0], bf[nt][1]);
                mma16(acc[1][nt], a[1][0], a[1][1], a[1][2], a[1][3], bf[nt][0], bf[nt][1]);
            }
        }
        __syncthreads();
        if (kt + 2 < 12) issue_tile(kt + 2);
    }

    if (QKV) {
        if (m0 < 768) {
            // Q or K rows -> transposed [b][h][n][d] half stores
            __half* T = (m0 < 384) ? g_QT : g_KT;
            const int cbase = (m0 < 384) ? 0 : 384;
#pragma unroll
            for (int jt = 0; jt < 2; jt++) {
                const int rb = m0 + mw * 32 + jt * 16 + gr;
                const int h = (rb - cbase) >> 5;
                const int d = rb & 31;
                const float bz0 = bias[rb], bz1 = bias[rb + 8];
                __half* Tb = T + (long)(b * 12 + h) * 1024 * 32;
#pragma unroll
                for (int nt = 0; nt < 8; nt++) {
                    const int cc = n0 + nw * 64 + nt * 8 + tc * 2;
                    Tb[(long)cc * 32 + d]           = __float2half_rn(acc[jt][nt][0] + bz0);
                    Tb[(long)(cc + 1) * 32 + d]     = __float2half_rn(acc[jt][nt][1] + bz0);
                    Tb[(long)cc * 32 + d + 8]       = __float2half_rn(acc[jt][nt][2] + bz1);
                    Tb[(long)(cc + 1) * 32 + d + 8] = __float2half_rn(acc[jt][nt][3] + bz1);
                }
            }
        } else {
            __half* Vb = g_V + (long)b * 384 * 1024;
#pragma unroll
            for (int jt = 0; jt < 2; jt++) {
                const int rb = m0 + mw * 32 + jt * 16 + gr;
                const int rv = rb - 768;
                const float bz0 = bias[rb], bz1 = bias[rb + 8];
#pragma unroll
                for (int nt = 0; nt < 8; nt++) {
                    const int cc = n0 + nw * 64 + nt * 8 + tc * 2;
                    *reinterpret_cast<__half2*>(Vb + (long)rv * 1024 + cc) =
                        __floats2half2_rn(acc[jt][nt][0] + bz0, acc[jt][nt][1] + bz0);
                    *reinterpret_cast<__half2*>(Vb + (long)(rv + 8) * 1024 + cc) =
                        __floats2half2_rn(acc[jt][nt][2] + bz1, acc[jt][nt][3] + bz1);
                }
            }
        }
    } else {
        float* Cb = (float*)Cout + (long)b * cStride;
#pragma unroll
        for (int jt = 0; jt < 2; jt++) {
            const int rb = m0 + mw * 32 + jt * 16 + gr;
            const float bz0 = bias[rb], bz1 = bias[rb + 8];
#pragma unroll
            for (int nt = 0; nt < 8; nt++) {
                const int cc = n0 + nw * 64 + nt * 8 + tc * 2;
                *reinterpret_cast<float2*>(Cb + (long)rb * 1024 + cc) =
                    make_float2(acc[jt][nt][0] + bz0, acc[jt][nt][1] + bz0);
                *reinterpret_cast<float2*>(Cb + (long)(rb + 8) * 1024 + cc) =
                    make_float2(acc[jt][nt][2] + bz1, acc[jt][nt][3] + bz1);
            }
        }
    }
}

// ---------------------------------------------------------------------------
// fp16 flash attention. Q,K smem [n][d] (stride 40 halves); V [d][n] (136).
// S C-frag (q=gr rows, keys 2tc,2tc+1) packs directly into the PV B-frag:
// O^T = V * P^T with zero shuffles and natural key order.
// Grid: (qblock 0..7, head 0..11, batch 0..7). 256 threads, 2 CTAs/SM.
// ---------------------------------------------------------------------------
constexpr int AQ_TILE = 128 * 40;          // halves
constexpr int AV_TILE = 32 * 136;          // halves
constexpr int AB_QS  = 0;                              // bytes
constexpr int AB_KS  = AQ_TILE * 2;                    // 10240
constexpr int AB_VS  = AB_KS + 2 * AQ_TILE * 2;        // 30720
constexpr int AB_RPB = AB_VS + 2 * AV_TILE * 2;        // 48128
constexpr int ATTN_SMEM_BYTES = AB_RPB + 3972 * 4;     // 64,016 B

__global__ __launch_bounds__(256, 2)
void attn_async_kernel(__half* __restrict__ Oout) {
    extern __shared__ char smc[];
    __half* Qs    = reinterpret_cast<__half*>(smc + AB_QS);
    __half* Ksb   = reinterpret_cast<__half*>(smc + AB_KS);
    __half* Vsb   = reinterpret_cast<__half*>(smc + AB_VS);
    float*  rpb_s = reinterpret_cast<float*>(smc + AB_RPB);

    const int qb = blockIdx.x, h = blockIdx.y, b = blockIdx.z;
    const int tid  = threadIdx.x;
    const int warp = tid >> 5, lane = tid & 31;
    const int gr = lane >> 2, tc = lane & 3;

    const __half* QgT = g_QT + (long)(b * 12 + h) * 1024 * 32 + (long)qb * 128 * 32;
    const __half* KgT = g_KT + (long)(b * 12 + h) * 1024 * 32;
    const __half* Vg  = g_V + (long)b * 384 * 1024 + (long)h * 32 * 1024;

    // ldmatrix lane offsets (bytes)
    const int r8 = lane & 7;
    const unsigned q_off = ((warp * 16 + (lane & 8) + r8) * 40 + ((lane & 16) >> 1)) * 2;
    const unsigned k_off = ((((lane & 16) >> 1) + r8) * 40 + (lane & 8)) * 2;
    const unsigned v_off = (((lane & 8) + r8) * 136 + ((lane & 16) >> 1)) * 2;
    const unsigned Qs_u32 = smem_u32(Qs), Ks_u32 = smem_u32(Ksb), Vs_u32 = smem_u32(Vsb);

    // Group 0: Q tile (128x32 h) + K block 0 + V block 0 + fp32 bias row
#pragma unroll
    for (int i = 0; i < 2; i++) {
        int idx = tid + i * 256;
        {   // Q,K: [n][d], rows of 32 halves = 4 chunks
            int n = idx >> 2, ch = (idx & 3) << 3;
            cp_async16(Qs + n * 40 + ch, QgT + (long)n * 32 + ch);
            cp_async16(Ksb + n * 40 + ch, KgT + (long)n * 32 + ch);
        }
        {   // V: [d][n], rows of 128 halves = 16 chunks
            int d = idx >> 4, ch = (idx & 15) << 3;
            cp_async16(Vsb + d * 136 + ch, Vg + (long)d * 1024 + ch);
        }
    }
    {
        const float* rpbh = g_rpbT + h * 3972;
        for (int i = tid * 4; i < 3972; i += 1024)
            cp_async16(rpb_s + i, rpbh + i);
    }
    cp_commit();

    float oaccT[2][2][4];   // [d-tile][q-group][c]; O^T rows=d, cols=q
#pragma unroll
    for (int mt = 0; mt < 2; mt++)
#pragma unroll
        for (int qt = 0; qt < 2; qt++) { oaccT[mt][qt][0] = 0.f; oaccT[mt][qt][1] = 0.f; oaccT[mt][qt][2] = 0.f; oaccT[mt][qt][3] = 0.f; }
    float mrun0 = -1e30f, mrun1 = -1e30f, lrun0 = 0.f, lrun1 = 0.f;

    // Analytic bias: idx = Abias(q) - Bm(m), Bm = (m>>5)*63 + (m&31)
    const int n0g = qb * 128 + warp * 16 + gr;
    const int Abias0 = ((n0g >> 5) + 31) * 63 + (n0g & 31) + 31;
    const int n1g = n0g + 8;
    const int Abias1 = ((n1g >> 5) + 31) * 63 + (n1g & 31) + 31;

    const float L2E = 1.4426950408889634f;

    for (int kb = 0; kb < 8; kb++) {
        if (kb < 7) {
            const int nb = kb + 1;
            __half* Kn = Ksb + (nb & 1) * AQ_TILE;
            __half* Vn = Vsb + (nb & 1) * AV_TILE;
#pragma unroll
            for (int i = 0; i < 2; i++) {
                int idx = tid + i * 256;
                {
                    int n = idx >> 2, ch = (idx & 3) << 3;
                    cp_async16(Kn + n * 40 + ch, KgT + (long)(nb * 128 + n) * 32 + ch);
                }
                {
                    int d = idx >> 4, ch = (idx & 15) << 3;
                    cp_async16(Vn + d * 136 + ch, Vg + (long)d * 1024 + nb * 128 + ch);
                }
            }
            cp_commit();
            cp_wait1();
        } else {
            cp_wait0();
        }
        __syncthreads();

        const unsigned Kbase = Ks_u32 + (kb & 1) * (AQ_TILE * 2) + k_off;
        const unsigned Vbase = Vs_u32 + (kb & 1) * (AV_TILE * 2) + v_off;

        // S = Q K^T: A = Q [q16][d16], B = K [key][d] via non-trans ldmatrix
        float sacc[16][4];
#pragma unroll
        for (int i = 0; i < 16; i++) { sacc[i][0] = 0.f; sacc[i][1] = 0.f; sacc[i][2] = 0.f; sacc[i][3] = 0.f; }

#pragma unroll
        for (int ks = 0; ks < 2; ks++) {
            const int kk = ks * 16;   // d offset (halves)
            unsigned a0, a1, a2, a3;
            ldsm_x4(a0, a1, a2, a3, Qs_u32 + q_off + kk * 2);
#pragma unroll
            for (int ntp = 0; ntp < 8; ntp++) {  // 16 keys per x4
                unsigned b00, b01, b10, b11;
                ldsm_x4(b00, b01, b10, b11, Kbase + (ntp * 16 * 40 + kk) * 2);
                mma16(sacc[2 * ntp],     a0, a1, a2, a3, b00, b01);
                mma16(sacc[2 * ntp + 1], a0, a1, a2, a3, b10, b11);
            }
        }

        // Bias: this thread's cols are j = nt*8 + 2tc, +1
#pragma unroll
        for (int nt = 0; nt < 16; nt++) {
            const int m  = kb * 128 + nt * 8 + tc * 2;
            const int Bm = (m >> 5) * 63 + (m & 31);
            sacc[nt][0] += rpb_s[Abias0 - Bm];
            sacc[nt][1] += rpb_s[Abias0 - Bm - 1];
            sacc[nt][2] += rpb_s[Abias1 - Bm];
            sacc[nt][3] += rpb_s[Abias1 - Bm - 1];
        }

        // Row max
        float mx0 = -1e30f, mx1 = -1e30f;
#pragma unroll
        for (int nt = 0; nt < 16; nt++) {
            mx0 = fmaxf(mx0, fmaxf(sacc[nt][0], sacc[nt][1]));
            mx1 = fmaxf(mx1, fmaxf(sacc[nt][2], sacc[nt][3]));
        }
        mx0 = fmaxf(mx0, __shfl_xor_sync(0xffffffffu, mx0, 1));
        mx0 = fmaxf(mx0, __shfl_xor_sync(0xffffffffu, mx0, 2));
        mx1 = fmaxf(mx1, __shfl_xor_sync(0xffffffffu, mx1, 1));
        mx1 = fmaxf(mx1, __shfl_xor_sync(0xffffffffu, mx1, 2));
        const float mnew0 = fmaxf(mrun0, mx0);
        const float mnew1 = fmaxf(mrun1, mx1);
        const float alpha0 = fast_ex2((mrun0 - mnew0) * L2E);
        const float alpha1 = fast_ex2((mrun1 - mnew1) * L2E);
        mrun0 = mnew0; mrun1 = mnew1;

        // Per-q-column alphas for O^T (cols q = 2tc, 2tc+1 within group)
        const float aq0 = __shfl_sync(0xffffffffu, alpha0, 8 * tc);      // q = 2tc
        const float aq1 = __shfl_sync(0xffffffffu, alpha0, 8 * tc + 4);  // q = 2tc+1
        const float aq2 = __shfl_sync(0xffffffffu, alpha1, 8 * tc);
        const float aq3 = __shfl_sync(0xffffffffu, alpha1, 8 * tc + 4);
#pragma unroll
        for (int mt = 0; mt < 2; mt++) {
            oaccT[mt][0][0] *= aq0; oaccT[mt][0][1] *= aq1;
            oaccT[mt][0][2] *= aq0; oaccT[mt][0][3] *= aq1;
            oaccT[mt][1][0] *= aq2; oaccT[mt][1][1] *= aq3;
            oaccT[mt][1][2] *= aq2; oaccT[mt][1][3] *= aq3;
        }

        // exp -> half2 P (native B-frag) -> O^T += V * P^T
        float sum0 = 0.f, sum1 = 0.f;
#pragma unroll
        for (int j = 0; j < 8; j++) {   // k-step = keys 16j..16j+15 (tiles 2j,2j+1)
            float p00 = fast_ex2((sacc[2 * j][0] - mnew0) * L2E);
            float p01 = fast_ex2((sacc[2 * j][1] - mnew0) * L2E);
            float p02 = fast_ex2((sacc[2 * j][2] - mnew1) * L2E);
            float p03 = fast_ex2((sacc[2 * j][3] - mnew1) * L2E);
            float p10 = fast_ex2((sacc[2 * j + 1][0] - mnew0) * L2E);
            float p11 = fast_ex2((sacc[2 * j + 1][1] - mnew0) * L2E);
            float p12 = fast_ex2((sacc[2 * j + 1][2] - mnew1) * L2E);
            float p13 = fast_ex2((sacc[2 * j + 1][3] - mnew1) * L2E);
            sum0 += p00 + p01 + p10 + p11;
            sum1 += p02 + p03 + p12 + p13;

            const unsigned u00 = h2u(__floats2half2_rn(p00, p01));  // q-grp 0, keys lo8
            const unsigned u01 = h2u(__floats2half2_rn(p10, p11));  // q-grp 0, keys hi8
            const unsigned u10 = h2u(__floats2half2_rn(p02, p03));  // q-grp 1, keys lo8
            const unsigned u11 = h2u(__floats2half2_rn(p12, p13));  // q-grp 1, keys hi8

#pragma unroll
            for (int mt = 0; mt < 2; mt++) {
                unsigned va0, va1, va2, va3;
                ldsm_x4(va0, va1, va2, va3, Vbase + (mt * 16 * 136 + j * 16) * 2);
                mma16(oaccT[mt][0], va0, va1, va2, va3, u00, u01);
                mma16(oaccT[mt][1], va0, va1, va2, va3, u10, u11);
            }
        }
        sum0 += __shfl_xor_sync(0xffffffffu, sum0, 1);
        sum0 += __shfl_xor_sync(0xffffffffu, sum0, 2);
        sum1 += __shfl_xor_sync(0xffffffffu, sum1, 1);
        sum1 += __shfl_xor_sync(0xffffffffu, sum1, 2);
        lrun0 = lrun0 * alpha0 + sum0;
        lrun1 = lrun1 * alpha1 + sum1;

        __syncthreads();  // all warps done with K/V[cur] before refill
    }

    // Finalize: per-q-column 1/l, direct half2 [d][n] stores
    const float inv0 = 1.f / lrun0;
    const float inv1 = 1.f / lrun1;
    const float iq0 = __shfl_sync(0xffffffffu, inv0, 8 * tc);
    const float iq1 = __shfl_sync(0xffffffffu, inv0, 8 * tc + 4);
    const float iq2 = __shfl_sync(0xffffffffu, inv1, 8 * tc);
    const float iq3 = __shfl_sync(0xffffffffu, inv1, 8 * tc + 4);

    __half* Ob = Oout + ((long)b * 384 + h * 32) * 1024 + qb * 128 + warp * 16;
#pragma unroll
    for (int mt = 0; mt < 2; mt++) {
#pragma unroll
        for (int qt = 0; qt < 2; qt++) {
            const float sA = qt ? iq2 : iq0;
            const float sB = qt ? iq3 : iq1;
            const int col = qt * 8 + tc * 2;
            const int r   = mt * 16 + gr;
            *reinterpret_cast<__half2*>(Ob + (long)r * 1024 + col) =
                __floats2half2_rn(oaccT[mt][qt][0] * sA, oaccT[mt][qt][1] * sB);
            *reinterpret_cast<__half2*>(Ob + (long)(r + 8) * 1024 + col) =
                __floats2half2_rn(oaccT[mt][qt][2] * sA, oaccT[mt][qt][3] * sB);
        }
    }
}

// ---------------------------------------------------------------------------
// Launch
// ---------------------------------------------------------------------------
extern "C" void kernel_launch(void* const* d_in, const int* in_sizes, int n_in,
                              void* d_out, int out_size) {
    (void)in_sizes; (void)n_in; (void)out_size;
    const float* x      = (const float*)d_in[0];
    const float* q_w    = (const float*)d_in[1];
    const float* q_b    = (const float*)d_in[2];
    const float* kv_w   = (const float*)d_in[3];
    const float* kv_b   = (const float*)d_in[4];
    const float* proj_w = (const float*)d_in[5];
    const float* proj_b = (const float*)d_in[6];
    const float* rpb    = (const float*)d_in[7];
    // d_in[8] = rel_index: recomputed analytically on device, unused.
    float* out = (float*)d_out;

    __half* X = nullptr; cudaGetSymbolAddress((void**)&X, g_X);
    __half* O = nullptr; cudaGetSymbolAddress((void**)&O, g_O);
    __half* Wqkv = nullptr; cudaGetSymbolAddress((void**)&Wqkv, g_Wqkv);
    __half* Wp   = nullptr; cudaGetSymbolAddress((void**)&Wp, g_Wp);
    float* Bqkv = nullptr; cudaGetSymbolAddress((void**)&Bqkv, g_Bqkv);

    cudaFuncSetAttribute(gemm_async_kernel<true>,
                         cudaFuncAttributeMaxDynamicSharedMemorySize, GEMM_SMEM_BYTES);
    cudaFuncSetAttribute(gemm_async_kernel<false>,
                         cudaFuncAttributeMaxDynamicSharedMemorySize, GEMM_SMEM_BYTES);
    cudaFuncSetAttribute(attn_async_kernel,
                         cudaFuncAttributeMaxDynamicSharedMemorySize, ATTN_SMEM_BYTES);

    dim3 blk(256);
    // Round operands to fp16 once (RN; 10-bit mantissa, same as tf32 path)
    convert_x_kernel<<<768, blk>>>(x);
    convert_w_kernel<<<288, blk>>>(q_w, kv_w, proj_w, q_b, kv_b, rpb);
    // Fused QKV projection: Q->g_QT, K->g_KT (transposed), V->g_V
    gemm_async_kernel<true><<<dim3(8, 9, 8), blk, GEMM_SMEM_BYTES>>>(
        Wqkv, X, Bqkv, nullptr, 384L * 1024, 0);
    // Flash attention -> g_O (half)
    attn_async_kernel<<<dim3(8, 12, 8), blk, ATTN_SMEM_BYTES>>>(O);
    // Output projection -> d_out (fp32)
    gemm_async_kernel<false><<<dim3(8, 3, 8), blk, GEMM_SMEM_BYTES>>>(
        Wp, O, proj_b, out, 384L * 1024, 384L * 1024);
}

// round 14
// speedup vs baseline: 1.7513x; 1.1572x over previous
#include <cuda_runtime.h>
#include <cuda_fp16.h>
#include <cstdint>

// ---------------------------------------------------------------------------
// Scratch (static __device__ — no allocation in kernel_launch)
// ---------------------------------------------------------------------------
static __device__ __half g_X[8 * 384 * 1024];        // fp16 input activations
static __device__ __half g_QT[8 * 12 * 1024 * 32];   // Q*scale*log2e, [b][h][n][d]
static __device__ __half g_KT[8 * 12 * 1024 * 32];   // K transposed [b][h][n][d]
static __device__ __half g_V[8 * 384 * 1024];        // V [b][c][n]
static __device__ __half g_O[8 * 384 * 1024];        // attention out [b][c][n]
static __device__ __half g_Wqkv[1152 * 384];         // [q_w*scale*log2e ; kv_w]
static __device__ __half g_Wp[384 * 384];            // proj_w
static __device__ float  g_Bqkv[1152];               // [q_b*scale*log2e ; kv_b]
static __device__ float  g_rpbT[12 * 3972];          // rpb^T * log2e [head][pad]

// ---------------------------------------------------------------------------
// Helpers
// ---------------------------------------------------------------------------
__device__ __forceinline__ float fast_ex2(float x) {
    float y;
    asm("ex2.approx.f32 %0, %1;" : "=f"(y) : "f"(x));
    return y;
}

// m16n8k16 fp16 mma, fp32 accumulate.
__device__ __forceinline__ void mma16(float* c,
                                      unsigned a0, unsigned a1, unsigned a2, unsigned a3,
                                      unsigned b0, unsigned b1) {
    asm volatile(
        "mma.sync.aligned.m16n8k16.row.col.f32.f16.f16.f32 "
        "{%0,%1,%2,%3}, {%4,%5,%6,%7}, {%8,%9}, {%0,%1,%2,%3};\n"
        : "+f"(c[0]), "+f"(c[1]), "+f"(c[2]), "+f"(c[3])
        : "r"(a0), "r"(a1), "r"(a2), "r"(a3), "r"(b0), "r"(b1));
}

__device__ __forceinline__ void ldsm_x4(unsigned& r0, unsigned& r1, unsigned& r2, unsigned& r3,
                                        unsigned addr) {
    asm volatile("ldmatrix.sync.aligned.m8n8.x4.shared.b16 {%0,%1,%2,%3}, [%4];\n"
                 : "=r"(r0), "=r"(r1), "=r"(r2), "=r"(r3) : "r"(addr));
}
__device__ __forceinline__ void ldsm_x4_t(unsigned& r0, unsigned& r1, unsigned& r2, unsigned& r3,
                                          unsigned addr) {
    asm volatile("ldmatrix.sync.aligned.m8n8.x4.trans.shared.b16 {%0,%1,%2,%3}, [%4];\n"
                 : "=r"(r0), "=r"(r1), "=r"(r2), "=r"(r3) : "r"(addr));
}

__device__ __forceinline__ unsigned smem_u32(const void* p) {
    return (unsigned)__cvta_generic_to_shared(p);
}
__device__ __forceinline__ void cp_async16(void* smem_dst, const void* gmem_src) {
    unsigned s = (unsigned)__cvta_generic_to_shared(smem_dst);
    asm volatile("cp.async.cg.shared.global [%0], [%1], 16;\n" :: "r"(s), "l"(gmem_src));
}
__device__ __forceinline__ void cp_commit() { asm volatile("cp.async.commit_group;\n"); }
__device__ __forceinline__ void cp_wait0() { asm volatile("cp.async.wait_group 0;\n"); }
__device__ __forceinline__ void cp_wait1() { asm volatile("cp.async.wait_group 1;\n"); }

__device__ __forceinline__ unsigned h2u(__half2 h) { return *reinterpret_cast<unsigned*>(&h); }

// ---------------------------------------------------------------------------
// One-time conversion kernels
// ---------------------------------------------------------------------------
__global__ void convert_x_kernel(const float* __restrict__ x) {
    const float4* src = reinterpret_cast<const float4*>(x);
    __half2* dst = reinterpret_cast<__half2*>(g_X);
    const int stride = gridDim.x * blockDim.x;
    for (int i = blockIdx.x * blockDim.x + threadIdx.x; i < 786432; i += stride) {
        float4 v = src[i];
        dst[2 * i]     = __floats2half2_rn(v.x, v.y);
        dst[2 * i + 1] = __floats2half2_rn(v.z, v.w);
    }
}

__global__ void convert_w_kernel(const float* __restrict__ qw, const float* __restrict__ kvw,
                                 const float* __restrict__ pw, const float* __restrict__ qb,
                                 const float* __restrict__ kvb, const float* __restrict__ rpb) {
    // Fold 32^-0.5 (attention scale) AND log2(e) into the Q path + bias table,
    // so softmax is a bare exp2 with no max subtraction.
    const float qscale = 0.17677669529663687f * 1.4426950408889634f;
    const float L2E = 1.4426950408889634f;
    const int stride = gridDim.x * blockDim.x;
    const int t = blockIdx.x * blockDim.x + threadIdx.x;
    for (int i = t; i < 147456; i += stride) g_Wqkv[i] = __float2half_rn(qw[i] * qscale);
    for (int i = t; i < 294912; i += stride) g_Wqkv[147456 + i] = __float2half_rn(kvw[i]);
    for (int i = t; i < 147456; i += stride) g_Wp[i] = __float2half_rn(pw[i]);
    for (int i = t; i < 384; i += stride) g_Bqkv[i] = qb[i] * qscale;
    for (int i = t; i < 768; i += stride) g_Bqkv[384 + i] = kvb[i];
    for (int i = t; i < 12 * 3969; i += stride) {
        int h = i / 3969, j = i - h * 3969;
        g_rpbT[h * 3972 + j] = rpb[j * 12 + h] * L2E;
    }
}

// ---------------------------------------------------------------------------
// Batched fp16 GEMM, cp.async 2-stage, all fragments via ldmatrix.
// C[b][m][n] = sum_k W[m][k] * X[b][k][n] + bias[m].  K=384, N=1024.
// Tiles 128x128, k-chunk 32 (2 mma k-steps). 8 warps 4(m)x2(n): 32x64/warp.
// ---------------------------------------------------------------------------
constexpr int GA_STRIDE = 40;    // halves per A row
constexpr int GB_STRIDE = 136;   // halves per B row
constexpr int GA_TILE = 128 * GA_STRIDE;
constexpr int GB_TILE = 32 * GB_STRIDE;
constexpr int GEMM_SMEM_BYTES = 2 * (GA_TILE + GB_TILE) * 2;  // 38,656 B

template <bool QKV>
__global__ __launch_bounds__(256, 2)
void gemm_async_kernel(const __half* __restrict__ W, const __half* __restrict__ X,
                       const float* __restrict__ bias, void* __restrict__ Cout,
                       long xStride, long cStride) {
    extern __shared__ __half smh[];
    __half* As = smh;
    __half* Bs = smh + 2 * GA_TILE;

    const int b  = blockIdx.z;
    const int m0 = blockIdx.y * 128;
    const int n0 = blockIdx.x * 128;
    const __half* Xb = X + (long)b * xStride;

    const int tid  = threadIdx.x;
    const int warp = tid >> 5, lane = tid & 31;
    const int gr = lane >> 2, tc = lane & 3;
    const int mw = warp >> 1, nw = warp & 1;

    const unsigned As_u32 = smem_u32(As), Bs_u32 = smem_u32(Bs);
    unsigned aoff[2];
#pragma unroll
    for (int jt = 0; jt < 2; jt++)
        aoff[jt] = ((mw * 32 + jt * 16 + (lane & 8) + (lane & 7)) * GA_STRIDE +
                    ((lane & 16) >> 1)) * 2;
    const unsigned boff = (((lane & 8) + (lane & 7)) * GB_STRIDE +
                           nw * 64 + ((lane & 16) ? 8 : 0)) * 2;

    auto issue_tile = [&](int kt) {
        __half* A  = As + (kt & 1) * GA_TILE;
        __half* Bt = Bs + (kt & 1) * GB_TILE;
        const int k0 = kt * 32;
#pragma unroll
        for (int i = 0; i < 2; i++) {
            int idx = tid + i * 256;
            int r = idx >> 2, ch = (idx & 3) << 3;
            cp_async16(A + r * GA_STRIDE + ch, W + (long)(m0 + r) * 384 + k0 + ch);
        }
#pragma unroll
        for (int i = 0; i < 2; i++) {
            int idx = tid + i * 256;
            int r = idx >> 4, ch = (idx & 15) << 3;
            cp_async16(Bt + r * GB_STRIDE + ch, Xb + (long)(k0 + r) * 1024 + n0 + ch);
        }
        cp_commit();
    };

    float acc[2][8][4];
#pragma unroll
    for (int j = 0; j < 2; j++)
#pragma unroll
        for (int i = 0; i < 8; i++) { acc[j][i][0] = 0.f; acc[j][i][1] = 0.f; acc[j][i][2] = 0.f; acc[j][i][3] = 0.f; }

    issue_tile(0);
    issue_tile(1);

    for (int kt = 0; kt < 12; kt++) {
        if (kt < 11) cp_wait1(); else cp_wait0();
        __syncthreads();

        const unsigned Abase = As_u32 + (kt & 1) * (GA_TILE * 2);
        const unsigned Bbase = Bs_u32 + (kt & 1) * (GB_TILE * 2);
#pragma unroll
        for (int ks = 0; ks < 2; ks++) {
            const int kk = ks * 16;
            unsigned a[2][4];
#pragma unroll
            for (int jt = 0; jt < 2; jt++)
                ldsm_x4(a[jt][0], a[jt][1], a[jt][2], a[jt][3], Abase + aoff[jt] + kk * 2);
            unsigned bf[8][2];
#pragma unroll
            for (int bi = 0; bi < 4; bi++)
                ldsm_x4_t(bf[2 * bi][0], bf[2 * bi][1], bf[2 * bi + 1][0], bf[2 * bi + 1][1],
                          Bbase + boff + (kk * GB_STRIDE + bi * 16) * 2);
#pragma unroll
            for (int nt = 0; nt < 8; nt++) {
                mma16(acc[0][nt], a[0][0], a[0][1], a[0][2], a[0][3], bf[nt][0], bf[nt][1]);
                mma16(acc[1][nt], a[1][0], a[1][1], a[1][2], a[1][3], bf[nt][0], bf[nt][1]);
            }
        }
        __syncthreads();
        if (kt + 2 < 12) issue_tile(kt + 2);
    }

    if (QKV) {
        if (m0 < 768) {
            __half* T = (m0 < 384) ? g_QT : g_KT;
            const int cbase = (m0 < 384) ? 0 : 384;
#pragma unroll
            for (int jt = 0; jt < 2; jt++) {
                const int rb = m0 + mw * 32 + jt * 16 + gr;
                const int h = (rb - cbase) >> 5;
                const int d = rb & 31;
                const float bz0 = bias[rb], bz1 = bias[rb + 8];
                __half* Tb = T + (long)(b * 12 + h) * 1024 * 32;
#pragma unroll
                for (int nt = 0; nt < 8; nt++) {
                    const int cc = n0 + nw * 64 + nt * 8 + tc * 2;
                    Tb[(long)cc * 32 + d]           = __float2half_rn(acc[jt][nt][0] + bz0);
                    Tb[(long)(cc + 1) * 32 + d]     = __float2half_rn(acc[jt][nt][1] + bz0);
                    Tb[(long)cc * 32 + d + 8]       = __float2half_rn(acc[jt][nt][2] + bz1);
                    Tb[(long)(cc + 1) * 32 + d + 8] = __float2half_rn(acc[jt][nt][3] + bz1);
                }
            }
        } else {
            __half* Vb = g_V + (long)b * 384 * 1024;
#pragma unroll
            for (int jt = 0; jt < 2; jt++) {
                const int rb = m0 + mw * 32 + jt * 16 + gr;
                const int rv = rb - 768;
                const float bz0 = bias[rb], bz1 = bias[rb + 8];
#pragma unroll
                for (int nt = 0; nt < 8; nt++) {
                    const int cc = n0 + nw * 64 + nt * 8 + tc * 2;
                    *reinterpret_cast<__half2*>(Vb + (long)rv * 1024 + cc) =
                        __floats2half2_rn(acc[jt][nt][0] + bz0, acc[jt][nt][1] + bz0);
                    *reinterpret_cast<__half2*>(Vb + (long)(rv + 8) * 1024 + cc) =
                        __floats2half2_rn(acc[jt][nt][2] + bz1, acc[jt][nt][3] + bz1);
                }
            }
        }
    } else {
        float* Cb = (float*)Cout + (long)b * cStride;
#pragma unroll
        for (int jt = 0; jt < 2; jt++) {
            const int rb = m0 + mw * 32 + jt * 16 + gr;
            const float bz0 = bias[rb], bz1 = bias[rb + 8];
#pragma unroll
            for (int nt = 0; nt < 8; nt++) {
                const int cc = n0 + nw * 64 + nt * 8 + tc * 2;
                *reinterpret_cast<float2*>(Cb + (long)rb * 1024 + cc) =
                    make_float2(acc[jt][nt][0] + bz0, acc[jt][nt][1] + bz0);
                *reinterpret_cast<float2*>(Cb + (long)(rb + 8) * 1024 + cc) =
                    make_float2(acc[jt][nt][2] + bz1, acc[jt][nt][3] + bz1);
            }
        }
    }
}

// ---------------------------------------------------------------------------
// fp16 flash attention, max-free softmax (scores provably tiny; log2e folded
// upstream). Fully fused per-16-key tile: S mma -> bias+exp2 -> pack -> PV mma,
// so S never lives whole => ~80 regs => 3 CTAs/SM.
// Grid: (qblock 0..7, head 0..11, batch 0..7). 256 threads.
// ---------------------------------------------------------------------------
constexpr int AQ_TILE = 128 * 40;          // halves
constexpr int AV_TILE = 32 * 136;          // halves
constexpr int AB_QS  = 0;                              // bytes
constexpr int AB_KS  = AQ_TILE * 2;                    // 10240
constexpr int AB_VS  = AB_KS + 2 * AQ_TILE * 2;        // 30720
constexpr int AB_RPB = AB_VS + 2 * AV_TILE * 2;        // 48128
constexpr int ATTN_SMEM_BYTES = AB_RPB + 3972 * 4;     // 64,016 B

__global__ __launch_bounds__(256, 3)
void attn_async_kernel(__half* __restrict__ Oout) {
    extern __shared__ char smc[];
    __half* Qs    = reinterpret_cast<__half*>(smc + AB_QS);
    __half* Ksb   = reinterpret_cast<__half*>(smc + AB_KS);
    __half* Vsb   = reinterpret_cast<__half*>(smc + AB_VS);
    float*  rpb_s = reinterpret_cast<float*>(smc + AB_RPB);

    const int qb = blockIdx.x, h = blockIdx.y, b = blockIdx.z;
    const int tid  = threadIdx.x;
    const int warp = tid >> 5, lane = tid & 31;
    const int gr = lane >> 2, tc = lane & 3;

    const __half* QgT = g_QT + (long)(b * 12 + h) * 1024 * 32 + (long)qb * 128 * 32;
    const __half* KgT = g_KT + (long)(b * 12 + h) * 1024 * 32;
    const __half* Vg  = g_V + (long)b * 384 * 1024 + (long)h * 32 * 1024;

    const int r8 = lane & 7;
    const unsigned q_off = ((warp * 16 + (lane & 8) + r8) * 40 + ((lane & 16) >> 1)) * 2;
    const unsigned k_off = ((((lane & 16) >> 1) + r8) * 40 + (lane & 8)) * 2;
    const unsigned v_off = (((lane & 8) + r8) * 136 + ((lane & 16) >> 1)) * 2;
    const unsigned Qs_u32 = smem_u32(Qs), Ks_u32 = smem_u32(Ksb), Vs_u32 = smem_u32(Vsb);

    // Group 0: Q tile + K block 0 + V block 0 + bias row
#pragma unroll
    for (int i = 0; i < 2; i++) {
        int idx = tid + i * 256;
        {
            int n = idx >> 2, ch = (idx & 3) << 3;
            cp_async16(Qs + n * 40 + ch, QgT + (long)n * 32 + ch);
            cp_async16(Ksb + n * 40 + ch, KgT + (long)n * 32 + ch);
        }
        {
            int d = idx >> 4, ch = (idx & 15) << 3;
            cp_async16(Vsb + d * 136 + ch, Vg + (long)d * 1024 + ch);
        }
    }
    {
        const float* rpbh = g_rpbT + h * 3972;
        for (int i = tid * 4; i < 3972; i += 1024)
            cp_async16(rpb_s + i, rpbh + i);
    }
    cp_commit();

    float oaccT[2][2][4];   // [d-tile][q-group][c]; O^T rows=d, cols=q
#pragma unroll
    for (int mt = 0; mt < 2; mt++)
#pragma unroll
        for (int qt = 0; qt < 2; qt++) { oaccT[mt][qt][0] = 0.f; oaccT[mt][qt][1] = 0.f; oaccT[mt][qt][2] = 0.f; oaccT[mt][qt][3] = 0.f; }
    float sum0 = 0.f, sum1 = 0.f;   // row sums, no rescaling needed

    // Analytic bias: idx = Abias(q) - Bm(m), Bm = (m>>5)*63 + (m&31)
    const int n0g = qb * 128 + warp * 16 + gr;
    const int Abias0 = ((n0g >> 5) + 31) * 63 + (n0g & 31) + 31;
    const int n1g = n0g + 8;
    const int Abias1 = ((n1g >> 5) + 31) * 63 + (n1g & 31) + 31;

    unsigned qa[2][4];   // Q fragments (constant across key blocks)

    for (int kb = 0; kb < 8; kb++) {
        if (kb < 7) {
            const int nb = kb + 1;
            __half* Kn = Ksb + (nb & 1) * AQ_TILE;
            __half* Vn = Vsb + (nb & 1) * AV_TILE;
#pragma unroll
            for (int i = 0; i < 2; i++) {
                int idx = tid + i * 256;
                {
                    int n = idx >> 2, ch = (idx & 3) << 3;
                    cp_async16(Kn + n * 40 + ch, KgT + (long)(nb * 128 + n) * 32 + ch);
                }
                {
                    int d = idx >> 4, ch = (idx & 15) << 3;
                    cp_async16(Vn + d * 136 + ch, Vg + (long)d * 1024 + nb * 128 + ch);
                }
            }
            cp_commit();
            cp_wait1();
        } else {
            cp_wait0();
        }
        __syncthreads();

        if (kb == 0) {
            ldsm_x4(qa[0][0], qa[0][1], qa[0][2], qa[0][3], Qs_u32 + q_off);
            ldsm_x4(qa[1][0], qa[1][1], qa[1][2], qa[1][3], Qs_u32 + q_off + 32);
        }

        const unsigned Kbase = Ks_u32 + (kb & 1) * (AQ_TILE * 2) + k_off;
        const unsigned Vbase = Vs_u32 + (kb & 1) * (AV_TILE * 2) + v_off;

        // Fused: per 16 keys -> S tiles -> exp2(S + bias) -> pack -> PV mma
#pragma unroll
        for (int j = 0; j < 8; j++) {
            unsigned kb00, kb01, kb10, kb11, kc00, kc01, kc10, kc11;
            ldsm_x4(kb00, kb01, kb10, kb11, Kbase + (j * 16 * 40) * 2);        // d 0..15
            ldsm_x4(kc00, kc01, kc10, kc11, Kbase + (j * 16 * 40 + 16) * 2);   // d 16..31

            float st0[4] = {0.f, 0.f, 0.f, 0.f};   // keys 16j+2tc(,+1), q rows gr/gr+8
            float st1[4] = {0.f, 0.f, 0.f, 0.f};   // keys 16j+8+2tc(,+1)
            mma16(st0, qa[0][0], qa[0][1], qa[0][2], qa[0][3], kb00, kb01);
            mma16(st0, qa[1][0], qa[1][1], qa[1][2], qa[1][3], kc00, kc01);
            mma16(st1, qa[0][0], qa[0][1], qa[0][2], qa[0][3], kb10, kb11);
            mma16(st1, qa[1][0], qa[1][1], qa[1][2], qa[1][3], kc10, kc11);

            const int mA = kb * 128 + j * 16 + tc * 2;
            const int BmA = (mA >> 5) * 63 + (mA & 31);
            const int mB = mA + 8;
            const int BmB = (mB >> 5) * 63 + (mB & 31);

            float p00 = fast_ex2(st0[0] + rpb_s[Abias0 - BmA]);
            float p01 = fast_ex2(st0[1] + rpb_s[Abias0 - BmA - 1]);
            float p02 = fast_ex2(st0[2] + rpb_s[Abias1 - BmA]);
            float p03 = fast_ex2(st0[3] + rpb_s[Abias1 - BmA - 1]);
            float p10 = fast_ex2(st1[0] + rpb_s[Abias0 - BmB]);
            float p11 = fast_ex2(st1[1] + rpb_s[Abias0 - BmB - 1]);
            float p12 = fast_ex2(st1[2] + rpb_s[Abias1 - BmB]);
            float p13 = fast_ex2(st1[3] + rpb_s[Abias1 - BmB - 1]);
            sum0 += p00 + p01 + p10 + p11;
            sum1 += p02 + p03 + p12 + p13;

            const unsigned u00 = h2u(__floats2half2_rn(p00, p01));  // q-grp 0, keys lo8
            const unsigned u01 = h2u(__floats2half2_rn(p10, p11));  // q-grp 0, keys hi8
            const unsigned u10 = h2u(__floats2half2_rn(p02, p03));  // q-grp 1, keys lo8
            const unsigned u11 = h2u(__floats2half2_rn(p12, p13));  // q-grp 1, keys hi8

            unsigned va0, va1, va2, va3;
            ldsm_x4(va0, va1, va2, va3, Vbase + (j * 16) * 2);
            mma16(oaccT[0][0], va0, va1, va2, va3, u00, u01);
            mma16(oaccT[0][1], va0, va1, va2, va3, u10, u11);
            ldsm_x4(va0, va1, va2, va3, Vbase + (16 * 136 + j * 16) * 2);
            mma16(oaccT[1][0], va0, va1, va2, va3, u00, u01);
            mma16(oaccT[1][1], va0, va1, va2, va3, u10, u11);
        }

        __syncthreads();  // all warps done with K/V[cur] before refill
    }

    // Final row-sum reduce (once, not per block) and normalization
    sum0 += __shfl_xor_sync(0xffffffffu, sum0, 1);
    sum0 += __shfl_xor_sync(0xffffffffu, sum0, 2);
    sum1 += __shfl_xor_sync(0xffffffffu, sum1, 1);
    sum1 += __shfl_xor_sync(0xffffffffu, sum1, 2);
    const float inv0 = 1.f / sum0;
    const float inv1 = 1.f / sum1;
    const float iq0 = __shfl_sync(0xffffffffu, inv0, 8 * tc);
    const float iq1 = __shfl_sync(0xffffffffu, inv0, 8 * tc + 4);
    const float iq2 = __shfl_sync(0xffffffffu, inv1, 8 * tc);
    const float iq3 = __shfl_sync(0xffffffffu, inv1, 8 * tc + 4);

    __half* Ob = Oout + ((long)b * 384 + h * 32) * 1024 + qb * 128 + warp * 16;
#pragma unroll
    for (int mt = 0; mt < 2; mt++) {
#pragma unroll
        for (int qt = 0; qt < 2; qt++) {
            const float sA = qt ? iq2 : iq0;
            const float sB = qt ? iq3 : iq1;
            const int col = qt * 8 + tc * 2;
            const int r   = mt * 16 + gr;
            *reinterpret_cast<__half2*>(Ob + (long)r * 1024 + col) =
                __floats2half2_rn(oaccT[mt][qt][0] * sA, oaccT[mt][qt][1] * sB);
            *reinterpret_cast<__half2*>(Ob + (long)(r + 8) * 1024 + col) =
                __floats2half2_rn(oaccT[mt][qt][2] * sA, oaccT[mt][qt][3] * sB);
        }
    }
}

// ---------------------------------------------------------------------------
// Launch
// ---------------------------------------------------------------------------
extern "C" void kernel_launch(void* const* d_in, const int* in_sizes, int n_in,
                              void* d_out, int out_size) {
    (void)in_sizes; (void)n_in; (void)out_size;
    const float* x      = (const float*)d_in[0];
    const float* q_w    = (const float*)d_in[1];
    const float* q_b    = (const float*)d_in[2];
    const float* kv_w   = (const float*)d_in[3];
    const float* kv_b   = (const float*)d_in[4];
    const float* proj_w = (const float*)d_in[5];
    const float* proj_b = (const float*)d_in[6];
    const float* rpb    = (const float*)d_in[7];
    // d_in[8] = rel_index: recomputed analytically on device, unused.
    float* out = (float*)d_out;

    __half* X = nullptr; cudaGetSymbolAddress((void**)&X, g_X);
    __half* O = nullptr; cudaGetSymbolAddress((void**)&O, g_O);
    __half* Wqkv = nullptr; cudaGetSymbolAddress((void**)&Wqkv, g_Wqkv);
    __half* Wp   = nullptr; cudaGetSymbolAddress((void**)&Wp, g_Wp);
    float* Bqkv = nullptr; cudaGetSymbolAddress((void**)&Bqkv, g_Bqkv);

    cudaFuncSetAttribute(gemm_async_kernel<true>,
                         cudaFuncAttributeMaxDynamicSharedMemorySize, GEMM_SMEM_BYTES);
    cudaFuncSetAttribute(gemm_async_kernel<false>,
                         cudaFuncAttributeMaxDynamicSharedMemorySize, GEMM_SMEM_BYTES);
    cudaFuncSetAttribute(attn_async_kernel,
                         cudaFuncAttributeMaxDynamicSharedMemorySize, ATTN_SMEM_BYTES);

    dim3 blk(256);
    convert_x_kernel<<<768, blk>>>(x);
    convert_w_kernel<<<288, blk>>>(q_w, kv_w, proj_w, q_b, kv_b, rpb);
    // Fused QKV projection: Q->g_QT, K->g_KT (transposed), V->g_V
    gemm_async_kernel<true><<<dim3(8, 9, 8), blk, GEMM_SMEM_BYTES>>>(
        Wqkv, X, Bqkv, nullptr, 384L * 1024, 0);
    // Flash attention -> g_O (half)
    attn_async_kernel<<<dim3(8, 12, 8), blk, ATTN_SMEM_BYTES>>>(O);
    // Output projection -> d_out (fp32)
    gemm_async_kernel<false><<<dim3(8, 3, 8), blk, GEMM_SMEM_BYTES>>>(
        Wp, O, proj_b, out, 384L * 1024, 384L * 1024);
}

// round 16
// speedup vs baseline: 1.8445x; 1.0532x over previous
#include <cuda_runtime.h>
#include <cuda_fp16.h>
#include <cstdint>

// ---------------------------------------------------------------------------
// Scratch (static __device__ — no allocation in kernel_launch)
// ---------------------------------------------------------------------------
static __device__ __half g_X[8 * 384 * 1024];        // fp16 input activations
static __device__ __half g_QT[8 * 12 * 1024 * 32];   // Q*scale*log2e, [b][h][n][d]
static __device__ __half g_KT[8 * 12 * 1024 * 32];   // K transposed [b][h][n][d]
static __device__ __half g_V[8 * 384 * 1024];        // V [b][c][n]
static __device__ __half g_O[8 * 384 * 1024];        // attention out [b][c][n]
static __device__ __half g_Wqkv[1152 * 384];         // [q_w*scale*log2e ; kv_w]
static __device__ __half g_Wp[384 * 384];            // proj_w
static __device__ float  g_Bqkv[1152];               // [q_b*scale*log2e ; kv_b]
static __device__ __half2 g_rpbH2[12 * 3972];        // (rpb[i], rpb[i-1])*log2e per head

// ---------------------------------------------------------------------------
// Helpers
// ---------------------------------------------------------------------------
// m16n8k16 fp16 mma, fp32 accumulate.
__device__ __forceinline__ void mma16(float* c,
                                      unsigned a0, unsigned a1, unsigned a2, unsigned a3,
                                      unsigned b0, unsigned b1) {
    asm volatile(
        "mma.sync.aligned.m16n8k16.row.col.f32.f16.f16.f32 "
        "{%0,%1,%2,%3}, {%4,%5,%6,%7}, {%8,%9}, {%0,%1,%2,%3};\n"
        : "+f"(c[0]), "+f"(c[1]), "+f"(c[2]), "+f"(c[3])
        : "r"(a0), "r"(a1), "r"(a2), "r"(a3), "r"(b0), "r"(b1));
}

__device__ __forceinline__ void ldsm_x4(unsigned& r0, unsigned& r1, unsigned& r2, unsigned& r3,
                                        unsigned addr) {
    asm volatile("ldmatrix.sync.aligned.m8n8.x4.shared.b16 {%0,%1,%2,%3}, [%4];\n"
                 : "=r"(r0), "=r"(r1), "=r"(r2), "=r"(r3) : "r"(addr));
}
__device__ __forceinline__ void ldsm_x4_t(unsigned& r0, unsigned& r1, unsigned& r2, unsigned& r3,
                                          unsigned addr) {
    asm volatile("ldmatrix.sync.aligned.m8n8.x4.trans.shared.b16 {%0,%1,%2,%3}, [%4];\n"
                 : "=r"(r0), "=r"(r1), "=r"(r2), "=r"(r3) : "r"(addr));
}

__device__ __forceinline__ unsigned smem_u32(const void* p) {
    return (unsigned)__cvta_generic_to_shared(p);
}
__device__ __forceinline__ void cp_async16(void* smem_dst, const void* gmem_src) {
    unsigned s = (unsigned)__cvta_generic_to_shared(smem_dst);
    asm volatile("cp.async.cg.shared.global [%0], [%1], 16;\n" :: "r"(s), "l"(gmem_src));
}
__device__ __forceinline__ void cp_commit() { asm volatile("cp.async.commit_group;\n"); }
__device__ __forceinline__ void cp_wait0() { asm volatile("cp.async.wait_group 0;\n"); }
__device__ __forceinline__ void cp_wait1() { asm volatile("cp.async.wait_group 1;\n"); }

__device__ __forceinline__ unsigned h2u(__half2 h) { return *reinterpret_cast<unsigned*>(&h); }

// packed half2 exp2
__device__ __forceinline__ unsigned h2ex2(unsigned x) {
    unsigned y;
    asm("ex2.approx.f16x2 %0, %1;" : "=r"(y) : "r"(x));
    return y;
}
__device__ __forceinline__ float fast_rcp(float x) {
    float y;
    asm("rcp.approx.f32 %0, %1;" : "=f"(y) : "f"(x));
    return y;
}

// ---------------------------------------------------------------------------
// One-time conversion kernels
// ---------------------------------------------------------------------------
__global__ void convert_x_kernel(const float* __restrict__ x) {
    const float4* src = reinterpret_cast<const float4*>(x);
    __half2* dst = reinterpret_cast<__half2*>(g_X);
    const int stride = gridDim.x * blockDim.x;
    for (int i = blockIdx.x * blockDim.x + threadIdx.x; i < 786432; i += stride) {
        float4 v = src[i];
        dst[2 * i]     = __floats2half2_rn(v.x, v.y);
        dst[2 * i + 1] = __floats2half2_rn(v.z, v.w);
    }
}

__global__ void convert_w_kernel(const float* __restrict__ qw, const float* __restrict__ kvw,
                                 const float* __restrict__ pw, const float* __restrict__ qb,
                                 const float* __restrict__ kvb, const float* __restrict__ rpb) {
    // Fold 32^-0.5 (attention scale) AND log2(e) into the Q path + bias table,
    // so softmax is a bare exp2 with no max subtraction.
    const float qscale = 0.17677669529663687f * 1.4426950408889634f;
    const float L2E = 1.4426950408889634f;
    const int stride = gridDim.x * blockDim.x;
    const int t = blockIdx.x * blockDim.x + threadIdx.x;
    for (int i = t; i < 147456; i += stride) g_Wqkv[i] = __float2half_rn(qw[i] * qscale);
    for (int i = t; i < 294912; i += stride) g_Wqkv[147456 + i] = __float2half_rn(kvw[i]);
    for (int i = t; i < 147456; i += stride) g_Wp[i] = __float2half_rn(pw[i]);
    for (int i = t; i < 384; i += stride) g_Bqkv[i] = qb[i] * qscale;
    for (int i = t; i < 768; i += stride) g_Bqkv[384 + i] = kvb[i];
    // Paired bias table: element i = (rpb[i], rpb[i-1]) * log2e as half2
    for (int i = t; i < 12 * 3969; i += stride) {
        int h = i / 3969, j = i - h * 3969;
        float bi = rpb[j * 12 + h] * L2E;
        float bm = (j > 0) ? rpb[(j - 1) * 12 + h] * L2E : 0.f;
        g_rpbH2[h * 3972 + j] = __floats2half2_rn(bi, bm);
    }
}

// ---------------------------------------------------------------------------
// Batched fp16 GEMM, cp.async 2-stage, all fragments via ldmatrix.
// C[b][m][n] = sum_k W[m][k] * X[b][k][n] + bias[m].  K=384, N=1024.
// Tiles 128x128, k-chunk 32 (2 mma k-steps). 8 warps 4(m)x2(n): 32x64/warp.
// ---------------------------------------------------------------------------
constexpr int GA_STRIDE = 40;    // halves per A row
constexpr int GB_STRIDE = 136;   // halves per B row
constexpr int GA_TILE = 128 * GA_STRIDE;
constexpr int GB_TILE = 32 * GB_STRIDE;
constexpr int GEMM_SMEM_BYTES = 2 * (GA_TILE + GB_TILE) * 2;  // 38,656 B

template <bool QKV>
__global__ __launch_bounds__(256, 2)
void gemm_async_kernel(const __half* __restrict__ W, const __half* __restrict__ X,
                       const float* __restrict__ bias, void* __restrict__ Cout,
                       long xStride, long cStride) {
    extern __shared__ __half smh[];
    __half* As = smh;
    __half* Bs = smh + 2 * GA_TILE;

    const int b  = blockIdx.z;
    const int m0 = blockIdx.y * 128;
    const int n0 = blockIdx.x * 128;
    const __half* Xb = X + (long)b * xStride;

    const int tid  = threadIdx.x;
    const int warp = tid >> 5, lane = tid & 31;
    const int gr = lane >> 2, tc = lane & 3;
    const int mw = warp >> 1, nw = warp & 1;

    const unsigned As_u32 = smem_u32(As), Bs_u32 = smem_u32(Bs);
    unsigned aoff[2];
#pragma unroll
    for (int jt = 0; jt < 2; jt++)
        aoff[jt] = ((mw * 32 + jt * 16 + (lane & 8) + (lane & 7)) * GA_STRIDE +
                    ((lane & 16) >> 1)) * 2;
    const unsigned boff = (((lane & 8) + (lane & 7)) * GB_STRIDE +
                           nw * 64 + ((lane & 16) ? 8 : 0)) * 2;

    auto issue_tile = [&](int kt) {
        __half* A  = As + (kt & 1) * GA_TILE;
        __half* Bt = Bs + (kt & 1) * GB_TILE;
        const int k0 = kt * 32;
#pragma unroll
        for (int i = 0; i < 2; i++) {
            int idx = tid + i * 256;
            int r = idx >> 2, ch = (idx & 3) << 3;
            cp_async16(A + r * GA_STRIDE + ch, W + (long)(m0 + r) * 384 + k0 + ch);
        }
#pragma unroll
        for (int i = 0; i < 2; i++) {
            int idx = tid + i * 256;
            int r = idx >> 4, ch = (idx & 15) << 3;
            cp_async16(Bt + r * GB_STRIDE + ch, Xb + (long)(k0 + r) * 1024 + n0 + ch);
        }
        cp_commit();
    };

    float acc[2][8][4];
#pragma unroll
    for (int j = 0; j < 2; j++)
#pragma unroll
        for (int i = 0; i < 8; i++) { acc[j][i][0] = 0.f; acc[j][i][1] = 0.f; acc[j][i][2] = 0.f; acc[j][i][3] = 0.f; }

    issue_tile(0);
    issue_tile(1);

    for (int kt = 0; kt < 12; kt++) {
        if (kt < 11) cp_wait1(); else cp_wait0();
        __syncthreads();

        const unsigned Abase = As_u32 + (kt & 1) * (GA_TILE * 2);
        const unsigned Bbase = Bs_u32 + (kt & 1) * (GB_TILE * 2);
#pragma unroll
        for (int ks = 0; ks < 2; ks++) {
            const int kk = ks * 16;
            unsigned a[2][4];
#pragma unroll
            for (int jt = 0; jt < 2; jt++)
                ldsm_x4(a[jt][0], a[jt][1], a[jt][2], a[jt][3], Abase + aoff[jt] + kk * 2);
            unsigned bf[8][2];
#pragma unroll
            for (int bi = 0; bi < 4; bi++)
                ldsm_x4_t(bf[2 * bi][0], bf[2 * bi][1], bf[2 * bi + 1][0], bf[2 * bi + 1][1],
                          Bbase + boff + (kk * GB_STRIDE + bi * 16) * 2);
#pragma unroll
            for (int nt = 0; nt < 8; nt++) {
                mma16(acc[0][nt], a[0][0], a[0][1], a[0][2], a[0][3], bf[nt][0], bf[nt][1]);
                mma16(acc[1][nt], a[1][0], a[1][1], a[1][2], a[1][3], bf[nt][0], bf[nt][1]);
            }
        }
        __syncthreads();
        if (kt + 2 < 12) issue_tile(kt + 2);
    }

    if (QKV) {
        if (m0 < 768) {
            __half* T = (m0 < 384) ? g_QT : g_KT;
            const int cbase = (m0 < 384) ? 0 : 384;
#pragma unroll
            for (int jt = 0; jt < 2; jt++) {
                const int rb = m0 + mw * 32 + jt * 16 + gr;
                const int h = (rb - cbase) >> 5;
                const int d = rb & 31;
                const float bz0 = bias[rb], bz1 = bias[rb + 8];
                __half* Tb = T + (long)(b * 12 + h) * 1024 * 32;
#pragma unroll
                for (int nt = 0; nt < 8; nt++) {
                    const int cc = n0 + nw * 64 + nt * 8 + tc * 2;
                    Tb[(long)cc * 32 + d]           = __float2half_rn(acc[jt][nt][0] + bz0);
                    Tb[(long)(cc + 1) * 32 + d]     = __float2half_rn(acc[jt][nt][1] + bz0);
                    Tb[(long)cc * 32 + d + 8]       = __float2half_rn(acc[jt][nt][2] + bz1);
                    Tb[(long)(cc + 1) * 32 + d + 8] = __float2half_rn(acc[jt][nt][3] + bz1);
                }
            }
        } else {
            __half* Vb = g_V + (long)b * 384 * 1024;
#pragma unroll
            for (int jt = 0; jt < 2; jt++) {
                const int rb = m0 + mw * 32 + jt * 16 + gr;
                const int rv = rb - 768;
                const float bz0 = bias[rb], bz1 = bias[rb + 8];
#pragma unroll
                for (int nt = 0; nt < 8; nt++) {
                    const int cc = n0 + nw * 64 + nt * 8 + tc * 2;
                    *reinterpret_cast<__half2*>(Vb + (long)rv * 1024 + cc) =
                        __floats2half2_rn(acc[jt][nt][0] + bz0, acc[jt][nt][1] + bz0);
                    *reinterpret_cast<__half2*>(Vb + (long)(rv + 8) * 1024 + cc) =
                        __floats2half2_rn(acc[jt][nt][2] + bz1, acc[jt][nt][3] + bz1);
                }
            }
        }
    } else {
        float* Cb = (float*)Cout + (long)b * cStride;
#pragma unroll
        for (int jt = 0; jt < 2; jt++) {
            const int rb = m0 + mw * 32 + jt * 16 + gr;
            const float bz0 = bias[rb], bz1 = bias[rb + 8];
#pragma unroll
            for (int nt = 0; nt < 8; nt++) {
                const int cc = n0 + nw * 64 + nt * 8 + tc * 2;
                *reinterpret_cast<float2*>(Cb + (long)rb * 1024 + cc) =
                    make_float2(acc[jt][nt][0] + bz0, acc[jt][nt][1] + bz0);
                *reinterpret_cast<float2*>(Cb + (long)(rb + 8) * 1024 + cc) =
                    make_float2(acc[jt][nt][2] + bz1, acc[jt][nt][3] + bz1);
            }
        }
    }
}

// ---------------------------------------------------------------------------
// fp16 flash attention, max-free softmax, half2 exp path, mma row-sums.
// Per 16-key tile: S mma -> pack fp32->half2 -> HADD2 bias pair ->
// ex2.f16x2 -> PV mma + all-ones sum mma. No shuffles anywhere.
// Grid: (qblock 0..7, head 0..11, batch 0..7). 256 threads, 3 CTAs/SM.
// ---------------------------------------------------------------------------
constexpr int AQ_TILE = 128 * 40;          // halves
constexpr int AV_TILE = 32 * 136;          // halves
constexpr int AB_QS  = 0;                              // bytes
constexpr int AB_KS  = AQ_TILE * 2;                    // 10240
constexpr int AB_VS  = AB_KS + 2 * AQ_TILE * 2;        // 30720
constexpr int AB_RPB = AB_VS + 2 * AV_TILE * 2;        // 48128
constexpr int ATTN_SMEM_BYTES = AB_RPB + 3972 * 4;     // 64,016 B

__global__ __launch_bounds__(256, 3)
void attn_async_kernel(__half* __restrict__ Oout) {
    extern __shared__ char smc[];
    __half*  Qs     = reinterpret_cast<__half*>(smc + AB_QS);
    __half*  Ksb    = reinterpret_cast<__half*>(smc + AB_KS);
    __half*  Vsb    = reinterpret_cast<__half*>(smc + AB_VS);
    __half2* rpb_s2 = reinterpret_cast<__half2*>(smc + AB_RPB);

    const int qb = blockIdx.x, h = blockIdx.y, b = blockIdx.z;
    const int tid  = threadIdx.x;
    const int warp = tid >> 5, lane = tid & 31;
    const int gr = lane >> 2, tc = lane & 3;

    const __half* QgT = g_QT + (long)(b * 12 + h) * 1024 * 32 + (long)qb * 128 * 32;
    const __half* KgT = g_KT + (long)(b * 12 + h) * 1024 * 32;
    const __half* Vg  = g_V + (long)b * 384 * 1024 + (long)h * 32 * 1024;

    const int r8 = lane & 7;
    const unsigned q_off = ((warp * 16 + (lane & 8) + r8) * 40 + ((lane & 16) >> 1)) * 2;
    const unsigned k_off = ((((lane & 16) >> 1) + r8) * 40 + (lane & 8)) * 2;
    const unsigned v_off = (((lane & 8) + r8) * 136 + ((lane & 16) >> 1)) * 2;
    const unsigned Qs_u32 = smem_u32(Qs), Ks_u32 = smem_u32(Ksb), Vs_u32 = smem_u32(Vsb);

    // Group 0: Q tile + K block 0 + V block 0 + paired bias table
#pragma unroll
    for (int i = 0; i < 2; i++) {
        int idx = tid + i * 256;
        {
            int n = idx >> 2, ch = (idx & 3) << 3;
            cp_async16(Qs + n * 40 + ch, QgT + (long)n * 32 + ch);
            cp_async16(Ksb + n * 40 + ch, KgT + (long)n * 32 + ch);
        }
        {
            int d = idx >> 4, ch = (idx & 15) << 3;
            cp_async16(Vsb + d * 136 + ch, Vg + (long)d * 1024 + ch);
        }
    }
    {
        const __half2* rpbh = g_rpbH2 + h * 3972;
        for (int i = tid * 4; i < 3972; i += 1024)
            cp_async16(rpb_s2 + i, rpbh + i);
    }
    cp_commit();

    float oaccT[2][2][4];   // [d-tile][q-group][c]; O^T rows=d, cols=q
#pragma unroll
    for (int mt = 0; mt < 2; mt++)
#pragma unroll
        for (int qt = 0; qt < 2; qt++) { oaccT[mt][qt][0] = 0.f; oaccT[mt][qt][1] = 0.f; oaccT[mt][qt][2] = 0.f; oaccT[mt][qt][3] = 0.f; }
    // Row sums per q column via all-ones mma: [q-group][c]
    float sumacc[2][4];
#pragma unroll
    for (int qt = 0; qt < 2; qt++) { sumacc[qt][0] = 0.f; sumacc[qt][1] = 0.f; sumacc[qt][2] = 0.f; sumacc[qt][3] = 0.f; }
    const unsigned ONES = 0x3C003C00u;   // half2(1,1)

    // Analytic bias: idx = Abias(q) - Bm(m), Bm = (m>>5)*63 + (m&31)
    const int n0g = qb * 128 + warp * 16 + gr;
    const int Abias0 = ((n0g >> 5) + 31) * 63 + (n0g & 31) + 31;
    const int n1g = n0g + 8;
    const int Abias1 = ((n1g >> 5) + 31) * 63 + (n1g & 31) + 31;

    unsigned qa[2][4];   // Q fragments (constant across key blocks)

    for (int kb = 0; kb < 8; kb++) {
        if (kb < 7) {
            const int nb = kb + 1;
            __half* Kn = Ksb + (nb & 1) * AQ_TILE;
            __half* Vn = Vsb + (nb & 1) * AV_TILE;
#pragma unroll
            for (int i = 0; i < 2; i++) {
                int idx = tid + i * 256;
                {
                    int n = idx >> 2, ch = (idx & 3) << 3;
                    cp_async16(Kn + n * 40 + ch, KgT + (long)(nb * 128 + n) * 32 + ch);
                }
                {
                    int d = idx >> 4, ch = (idx & 15) << 3;
                    cp_async16(Vn + d * 136 + ch, Vg + (long)d * 1024 + nb * 128 + ch);
                }
            }
            cp_commit();
            cp_wait1();
        } else {
            cp_wait0();
        }
        __syncthreads();

        if (kb == 0) {
            ldsm_x4(qa[0][0], qa[0][1], qa[0][2], qa[0][3], Qs_u32 + q_off);
            ldsm_x4(qa[1][0], qa[1][1], qa[1][2], qa[1][3], Qs_u32 + q_off + 32);
        }

        const unsigned Kbase = Ks_u32 + (kb & 1) * (AQ_TILE * 2) + k_off;
        const unsigned Vbase = Vs_u32 + (kb & 1) * (AV_TILE * 2) + v_off;

        // Fused: per 16 keys -> S mma -> half2 bias+exp2 -> PV mma + sum mma
#pragma unroll
        for (int j = 0; j < 8; j++) {
            unsigned kb00, kb01, kb10, kb11, kc00, kc01, kc10, kc11;
            ldsm_x4(kb00, kb01, kb10, kb11, Kbase + (j * 16 * 40) * 2);        // d 0..15
            ldsm_x4(kc00, kc01, kc10, kc11, Kbase + (j * 16 * 40 + 16) * 2);   // d 16..31

            float st0[4] = {0.f, 0.f, 0.f, 0.f};   // keys 16j+2tc(,+1)
            float st1[4] = {0.f, 0.f, 0.f, 0.f};   // keys 16j+8+2tc(,+1)
            mma16(st0, qa[0][0], qa[0][1], qa[0][2], qa[0][3], kb00, kb01);
            mma16(st0, qa[1][0], qa[1][1], qa[1][2], qa[1][3], kc00, kc01);
            mma16(st1, qa[0][0], qa[0][1], qa[0][2], qa[0][3], kb10, kb11);
            mma16(st1, qa[1][0], qa[1][1], qa[1][2], qa[1][3], kc10, kc11);

            const int mA = kb * 128 + j * 16 + tc * 2;
            const int BmA = (mA >> 5) * 63 + (mA & 31);
            const int mB = mA + 8;
            const int BmB = (mB >> 5) * 63 + (mB & 31);

            // paired bias loads: (bias[idx], bias[idx-1]) as half2
            const __half2 b00 = rpb_s2[Abias0 - BmA];
            const __half2 b01 = rpb_s2[Abias0 - BmB];
            const __half2 b10 = rpb_s2[Abias1 - BmA];
            const __half2 b11 = rpb_s2[Abias1 - BmB];

            // pack S to half2, add bias, exp2 — results ARE the PV B-frags
            const unsigned u00 = h2ex2(h2u(__hadd2(__floats2half2_rn(st0[0], st0[1]), b00)));
            const unsigned u01 = h2ex2(h2u(__hadd2(__floats2half2_rn(st1[0], st1[1]), b01)));
            const unsigned u10 = h2ex2(h2u(__hadd2(__floats2half2_rn(st0[2], st0[3]), b10)));
            const unsigned u11 = h2ex2(h2u(__hadd2(__floats2half2_rn(st1[2], st1[3]), b11)));

            unsigned va0, va1, va2, va3;
            ldsm_x4(va0, va1, va2, va3, Vbase + (j * 16) * 2);
            mma16(oaccT[0][0], va0, va1, va2, va3, u00, u01);
            mma16(oaccT[0][1], va0, va1, va2, va3, u10, u11);
            ldsm_x4(va0, va1, va2, va3, Vbase + (16 * 136 + j * 16) * 2);
            mma16(oaccT[1][0], va0, va1, va2, va3, u00, u01);
            mma16(oaccT[1][1], va0, va1, va2, va3, u10, u11);

            // row sums: C += ones * P^T  (every C row = per-q-column sum)
            mma16(sumacc[0], ONES, ONES, ONES, ONES, u00, u01);
            mma16(sumacc[1], ONES, ONES, ONES, ONES, u10, u11);
        }

        __syncthreads();  // all warps done with K/V[cur] before refill
    }

    // Normalize: sums already per-q-column in each thread. No shuffles.
    const float iq0 = fast_rcp(sumacc[0][0]);   // q col 2tc   (group 0)
    const float iq1 = fast_rcp(sumacc[0][1]);   // q col 2tc+1
    const float iq2 = fast_rcp(sumacc[1][0]);   // q col 8+2tc (group 1)
    const float iq3 = fast_rcp(sumacc[1][1]);

    __half* Ob = Oout + ((long)b * 384 + h * 32) * 1024 + qb * 128 + warp * 16;
#pragma unroll
    for (int mt = 0; mt < 2; mt++) {
#pragma unroll
        for (int qt = 0; qt < 2; qt++) {
            const float sA = qt ? iq2 : iq0;
            const float sB = qt ? iq3 : iq1;
            const int col = qt * 8 + tc * 2;
            const int r   = mt * 16 + gr;
            *reinterpret_cast<__half2*>(Ob + (long)r * 1024 + col) =
                __floats2half2_rn(oaccT[mt][qt][0] * sA, oaccT[mt][qt][1] * sB);
            *reinterpret_cast<__half2*>(Ob + (long)(r + 8) * 1024 + col) =
                __floats2half2_rn(oaccT[mt][qt][2] * sA, oaccT[mt][qt][3] * sB);
        }
    }
}

// ---------------------------------------------------------------------------
// Launch
// ---------------------------------------------------------------------------
extern "C" void kernel_launch(void* const* d_in, const int* in_sizes, int n_in,
                              void* d_out, int out_size) {
    (void)in_sizes; (void)n_in; (void)out_size;
    const float* x      = (const float*)d_in[0];
    const float* q_w    = (const float*)d_in[1];
    const float* q_b    = (const float*)d_in[2];
    const float* kv_w   = (const float*)d_in[3];
    const float* kv_b   = (const float*)d_in[4];
    const float* proj_w = (const float*)d_in[5];
    const float* proj_b = (const float*)d_in[6];
    const float* rpb    = (const float*)d_in[7];
    // d_in[8] = rel_index: recomputed analytically on device, unused.
    float* out = (float*)d_out;

    __half* X = nullptr; cudaGetSymbolAddress((void**)&X, g_X);
    __half* O = nullptr; cudaGetSymbolAddress((void**)&O, g_O);
    __half* Wqkv = nullptr; cudaGetSymbolAddress((void**)&Wqkv, g_Wqkv);
    __half* Wp   = nullptr; cudaGetSymbolAddress((void**)&Wp, g_Wp);
    float* Bqkv = nullptr; cudaGetSymbolAddress((void**)&Bqkv, g_Bqkv);

    cudaFuncSetAttribute(gemm_async_kernel<true>,
                         cudaFuncAttributeMaxDynamicSharedMemorySize, GEMM_SMEM_BYTES);
    cudaFuncSetAttribute(gemm_async_kernel<false>,
                         cudaFuncAttributeMaxDynamicSharedMemorySize, GEMM_SMEM_BYTES);
    cudaFuncSetAttribute(attn_async_kernel,
                         cudaFuncAttributeMaxDynamicSharedMemorySize, ATTN_SMEM_BYTES);

    dim3 blk(256);
    convert_x_kernel<<<768, blk>>>(x);
    convert_w_kernel<<<288, blk>>>(q_w, kv_w, proj_w, q_b, kv_b, rpb);
    // Fused QKV projection: Q->g_QT, K->g_KT (transposed), V->g_V
    gemm_async_kernel<true><<<dim3(8, 9, 8), blk, GEMM_SMEM_BYTES>>>(
        Wqkv, X, Bqkv, nullptr, 384L * 1024, 0);
    // Flash attention -> g_O (half)
    attn_async_kernel<<<dim3(8, 12, 8), blk, ATTN_SMEM_BYTES>>>(O);
    // Output projection -> d_out (fp32)
    gemm_async_kernel<false><<<dim3(8, 3, 8), blk, GEMM_SMEM_BYTES>>>(
        Wp, O, proj_b, out, 384L * 1024, 384L * 1024);
}